// round 1
// baseline (speedup 1.0000x reference)
#include <cuda_runtime.h>
#include <math.h>
#include <stdint.h>

// ---------------- problem constants ----------------
constexpr int NHc = 16;
constexpr int HDc = 64;
constexpr int Kc  = 16;
constexpr int Bc  = 4;
constexpr int Lc  = 2048;
constexpr int Cc  = 1024;      // NH*HD
constexpr int NCc = Lc / Kc;   // 128
constexpr int F4c = 4 * HDc;   // 256
constexpr int Mtok = Bc * Lc;  // 8192

// ---------------- scratch (device globals; no allocation allowed) ----------
__device__ float g_q [Bc*Lc*Cc];
__device__ float g_k [Bc*Lc*Cc];
__device__ float g_v [Bc*Lc*Cc];
__device__ float g_xq[Bc*Lc*Cc];   // (b,h,n,k,d)
__device__ float g_xk[Bc*Lc*Cc];
__device__ float g_xv[Bc*Lc*Cc];
__device__ float g_xqw[Bc*Lc*Cc];  // scan output (b,h,n,k,d)
__device__ float g_h2[Bc*Lc*Cc];   // post-norm hidden (b,l,c)
__device__ float g_lr[Bc*NHc*NCc*Kc];

// ---------------- helpers ----------------
__device__ __forceinline__ float wsum(float v) {
    #pragma unroll
    for (int o = 16; o; o >>= 1) v += __shfl_xor_sync(0xffffffffu, v, o);
    return v;
}
__device__ __forceinline__ float gelu_f(float x) {
    float x2 = x * x;
    float tt = tanhf(0.79788456f * x * (1.0f + 0.044715f * x2));
    return 0.5f * x * (1.0f + tt);
}
__device__ __forceinline__ float gelu_bwd_f(float x) {
    float x2 = x * x;
    float tt = tanhf(0.79788456f * x * (1.0f + 0.044715f * x2));
    return 0.5f * x * ((1.0f - tt * tt) * (0.79788456f + 0.1070322243f * x2))
         + 0.5f * (1.0f + tt);
}

// ---------------- GEMM: C[m][n] = sum_k A[m][k] * Bw[n][k]  (M=8192,N=1024,K=1024)
__device__ __forceinline__ void gemm_body(const float* __restrict__ A,
                                          const float* __restrict__ Bw,
                                          float* __restrict__ Co) {
    __shared__ float As[16][68];
    __shared__ float Bs[16][68];
    const int t  = threadIdx.x;
    const int tx = t & 15, ty = t >> 4;
    const int m0 = blockIdx.y * 64, n0 = blockIdx.x * 64;
    const int r  = t >> 2, q = t & 3;
    float acc[4][4] = {};
    for (int k0 = 0; k0 < 1024; k0 += 16) {
        float4 a4 = *(const float4*)(A  + (size_t)(m0 + r) * 1024 + k0 + q * 4);
        float4 b4 = *(const float4*)(Bw + (size_t)(n0 + r) * 1024 + k0 + q * 4);
        As[q*4+0][r] = a4.x; As[q*4+1][r] = a4.y; As[q*4+2][r] = a4.z; As[q*4+3][r] = a4.w;
        Bs[q*4+0][r] = b4.x; Bs[q*4+1][r] = b4.y; Bs[q*4+2][r] = b4.z; Bs[q*4+3][r] = b4.w;
        __syncthreads();
        #pragma unroll
        for (int kk = 0; kk < 16; kk++) {
            float4 av = *(const float4*)&As[kk][ty * 4];
            float4 bv = *(const float4*)&Bs[kk][tx * 4];
            float ar[4] = {av.x, av.y, av.z, av.w};
            float br[4] = {bv.x, bv.y, bv.z, bv.w};
            #pragma unroll
            for (int i = 0; i < 4; i++)
                #pragma unroll
                for (int j = 0; j < 4; j++) acc[i][j] += ar[i] * br[j];
        }
        __syncthreads();
    }
    #pragma unroll
    for (int i = 0; i < 4; i++) {
        float4 o = make_float4(acc[i][0], acc[i][1], acc[i][2], acc[i][3]);
        *(float4*)(Co + (size_t)(m0 + ty * 4 + i) * 1024 + n0 + tx * 4) = o;
    }
}

__global__ __launch_bounds__(256) void gemm_qkv_kernel(const float* __restrict__ hs,
                                                       const float* __restrict__ wq,
                                                       const float* __restrict__ wk,
                                                       const float* __restrict__ wv) {
    const float* w = (blockIdx.z == 0) ? wq : (blockIdx.z == 1) ? wk : wv;
    float* o = (blockIdx.z == 0) ? g_q : (blockIdx.z == 1) ? g_k : g_v;
    gemm_body(hs, w, o);
}

__global__ __launch_bounds__(256) void gemm_out_kernel(const float* __restrict__ wo,
                                                       float* __restrict__ out) {
    gemm_body(g_h2, wo, out);
}

// ---------------- prep: ttt_lr sigmoid + RoPE + relayout --------------------
__global__ __launch_bounds__(128) void prep_kernel(const float* __restrict__ hs,
                                                   const float* __restrict__ lrw,
                                                   const float* __restrict__ lrb) {
    const int m  = blockIdx.x;           // token
    const int b  = m >> 11;
    const int l  = m & 2047;
    const int n  = l >> 4, kk = l & 15;
    __shared__ float xrow[1024];
    const int t = threadIdx.x;
    for (int i = t; i < 1024; i += 128) xrow[i] = hs[(size_t)m * 1024 + i];
    __syncthreads();
    const int wp = t >> 5, lane = t & 31;
    #pragma unroll
    for (int s = 0; s < 4; s++) {
        int h = wp * 4 + s;
        float acc = 0.f;
        for (int c = lane; c < 1024; c += 32) acc += xrow[c] * lrw[h * 1024 + c];
        acc = wsum(acc);
        if (lane == 0) {
            float z = acc + lrb[h];
            g_lr[(((size_t)b * NHc + h) * NCc + n) * Kc + kk] = 1.0f / (1.0f + expf(-z));
        }
    }
    // RoPE (pairs (2i, 2i+1) rotated by (l%16) * 10000^(-2i/64))
    const float pos = (float)kk;
    for (int pr = t; pr < 512; pr += 128) {
        int h = pr >> 5, i = pr & 31;
        float inv = expf(-(float)(2 * i) * (1.0f / 64.0f) * 9.210340371976184f);
        float sn, cs;
        sincosf(pos * inv, &sn, &cs);
        size_t lin = (size_t)m * 1024 + h * 64 + 2 * i;
        size_t so  = ((((size_t)b * NHc + h) * NCc + n) * Kc + kk) * HDc + 2 * i;
        float qe = g_q[lin], qo = g_q[lin + 1];
        g_xq[so]     = qe * cs - qo * sn;
        g_xq[so + 1] = qo * cs + qe * sn;
        float ke = g_k[lin], ko = g_k[lin + 1];
        g_xk[so]     = ke * cs - ko * sn;
        g_xk[so + 1] = ko * cs + ke * sn;
    }
    for (int i = t; i < 1024; i += 128) {
        int h = i >> 6, d = i & 63;
        g_xv[((((size_t)b * NHc + h) * NCc + n) * Kc + kk) * HDc + d] = g_v[(size_t)m * 1024 + i];
    }
}

// ---------------- scan kernel ----------------
constexpr int SX = 68;    // stride for 16x64 buffers (float4-aligned, padded)
constexpr int SZ = 257;   // stride for 16x256 buffers (odd: conflict-free row access)
constexpr int SCAN_SMEM_FLOATS =
    64 * 256 + 256 * 65 + 256 + 64 + 64 + 64 + 6 * 16 * SX + 3 * 16 * SZ + 256 + 256 + 16 + 16;
constexpr int SCAN_SMEM_BYTES = SCAN_SMEM_FLOATS * 4;

__global__ __launch_bounds__(256, 1) void scan_kernel(
    const float* __restrict__ lti, const float* __restrict__ W1g,
    const float* __restrict__ b1g, const float* __restrict__ W2g,
    const float* __restrict__ b2g, const float* __restrict__ nw,
    const float* __restrict__ nb) {
    extern __shared__ float sm[];
    float* W1  = sm;                  // [64][256]
    float* W2  = W1 + 64 * 256;       // [256][65]
    float* b1s = W2 + 256 * 65;       // [256]
    float* b2s = b1s + 256;           // [64]
    float* gam = b2s + 64;            // [64]
    float* bet = gam + 64;            // [64]
    float* xq  = bet + 64;            // [16][SX]
    float* xk  = xq + 16 * SX;
    float* xv  = xk + 16 * SX;
    float* Z2  = xv + 16 * SX;
    float* gZ2 = Z2 + 16 * SX;
    float* Z2b = gZ2 + 16 * SX;
    float* Z1  = Z2b + 16 * SX;       // [16][SZ] (Z1, then X2_bar)
    float* X2  = Z1 + 16 * SZ;
    float* gZ1 = X2 + 16 * SZ;
    float* A1  = gZ1 + 16 * SZ;       // [16][16]
    float* A2  = A1 + 256;
    float* lrs = A2 + 256;            // [16]
    float* tok = lrs + 16;            // [16]

    const int t  = threadIdx.x;
    const int bh = blockIdx.x;
    const int hh = bh & 15;
    const int wp = t >> 5, lane = t & 31;

    for (int i = t; i < 64 * 256; i += 256) W1[i] = W1g[hh * 64 * 256 + i];
    for (int i = t; i < 256 * 64; i += 256) W2[(i >> 6) * 65 + (i & 63)] = W2g[hh * 256 * 64 + i];
    b1s[t] = b1g[hh * 256 + t];
    if (t < 64) { b2s[t] = b2g[hh * 64 + t]; gam[t] = nw[hh * 64 + t]; bet[t] = nb[hh * 64 + t]; }
    if (t < 16) tok[t] = fmaxf(1.0f / (float)(t + 1) + lti[t], 0.0f);
    __syncthreads();

    for (int n = 0; n < NCc; n++) {
        const size_t cb = ((size_t)bh * NCc + n) * (Kc * HDc);
        for (int i = t; i < 1024; i += 256) {
            int kk = i >> 6, d = i & 63;
            xq[kk * SX + d] = g_xq[cb + i];
            xk[kk * SX + d] = g_xk[cb + i];
            xv[kk * SX + d] = g_xv[cb + i];
        }
        if (t < 16) lrs[t] = g_lr[((size_t)bh * NCc + n) * Kc + t] * (1.0f / 64.0f);
        __syncthreads();

        // --- Z1 = xk @ W1 + b1 ;  X2 = gelu(Z1)  (thread t = column) ---
        {
            float acc[16];
            float bv = b1s[t];
            #pragma unroll
            for (int k = 0; k < 16; k++) acc[k] = bv;
            #pragma unroll
            for (int d = 0; d < 64; d += 4) {
                float w0 = W1[d * 256 + t], w1 = W1[(d + 1) * 256 + t];
                float w2 = W1[(d + 2) * 256 + t], w3 = W1[(d + 3) * 256 + t];
                #pragma unroll
                for (int k = 0; k < 16; k++) {
                    float4 x4 = *(const float4*)&xk[k * SX + d];
                    acc[k] += x4.x * w0 + x4.y * w1 + x4.z * w2 + x4.w * w3;
                }
            }
            #pragma unroll
            for (int k = 0; k < 16; k++) { Z1[k * SZ + t] = acc[k]; X2[k * SZ + t] = gelu_f(acc[k]); }
        }
        __syncthreads();

        // --- Z2 = X2 @ W2 + b2 (4 rows/thread) ;  A1 = tril(e*(xq@xk.T + 1)) ---
        {
            const int j = t & 63, rg = t >> 6;
            float acc[4];
            float bv = b2s[j];
            #pragma unroll
            for (int r = 0; r < 4; r++) acc[r] = bv;
            for (int f = 0; f < 256; f++) {
                float w = W2[f * 65 + j];
                #pragma unroll
                for (int r = 0; r < 4; r++) acc[r] += X2[(rg * 4 + r) * SZ + f] * w;
            }
            #pragma unroll
            for (int r = 0; r < 4; r++) Z2[(rg * 4 + r) * SX + j] = acc[r];

            const int ii = t >> 4, jj = t & 15;
            float s = 0.f;
            #pragma unroll
            for (int d = 0; d < 64; d += 4) {
                float4 a = *(const float4*)&xq[ii * SX + d];
                float4 c = *(const float4*)&xk[jj * SX + d];
                s += a.x * c.x + a.y * c.y + a.z * c.z + a.w * c.w;
            }
            A1[ii * 16 + jj] = (jj <= ii) ? tok[ii] * lrs[jj] * (s + 1.0f) : 0.0f;
        }
        __syncthreads();

        // --- gZ2 = ln_fused_l2_bwd(Z2, xv-xk)  (8 warps x 2 rows) ---
        #pragma unroll
        for (int rr = 0; rr < 2; rr++) {
            int k = wp * 2 + rr;
            float z0 = Z2[k * SX + lane], z1 = Z2[k * SX + lane + 32];
            float mu = wsum(z0 + z1) * (1.0f / 64.0f);
            float d0 = z0 - mu, d1 = z1 - mu;
            float var = wsum(d0 * d0 + d1 * d1) * (1.0f / 64.0f);
            float rstd = rsqrtf(var + 1e-6f);
            float xh0 = d0 * rstd, xh1 = d1 * rstd;
            float g0 = gam[lane], g1 = gam[lane + 32];
            float be0 = bet[lane], be1 = bet[lane + 32];
            float tg0 = xv[k * SX + lane] - xk[k * SX + lane];
            float tg1 = xv[k * SX + lane + 32] - xk[k * SX + lane + 32];
            float go0 = (g0 * xh0 + be0 - tg0) * g0;
            float go1 = (g1 * xh1 + be1 - tg1) * g1;
            float sgo = wsum(go0 + go1);
            float sgx = wsum(go0 * xh0 + go1 * xh1);
            float cc = rstd * (1.0f / 64.0f);
            gZ2[k * SX + lane]      = (64.0f * go0 - sgo - xh0 * sgx) * cc;
            gZ2[k * SX + lane + 32] = (64.0f * go1 - sgo - xh1 * sgx) * cc;
        }
        __syncthreads();

        // --- gZ1 = (gZ2 @ W2^T) * gelu_bwd(Z1)  (thread t = column f) ---
        {
            float acc[16] = {};
            #pragma unroll
            for (int j = 0; j < 64; j += 4) {
                float w0 = W2[t * 65 + j],     w1 = W2[t * 65 + j + 1];
                float w2 = W2[t * 65 + j + 2], w3 = W2[t * 65 + j + 3];
                #pragma unroll
                for (int k = 0; k < 16; k++) {
                    float4 g4 = *(const float4*)&gZ2[k * SX + j];
                    acc[k] += g4.x * w0 + g4.y * w1 + g4.z * w2 + g4.w * w3;
                }
            }
            #pragma unroll
            for (int k = 0; k < 16; k++) gZ1[k * SZ + t] = acc[k] * gelu_bwd_f(Z1[k * SZ + t]);
        }
        __syncthreads();

        // --- X2_bar = gelu(xq@W1 + b1 - A1@gZ1)   (stored into Z1 buffer) ---
        {
            float acc[16];
            float bv = b1s[t];
            #pragma unroll
            for (int k = 0; k < 16; k++) acc[k] = bv;
            #pragma unroll
            for (int d = 0; d < 64; d += 4) {
                float w0 = W1[d * 256 + t], w1 = W1[(d + 1) * 256 + t];
                float w2 = W1[(d + 2) * 256 + t], w3 = W1[(d + 3) * 256 + t];
                #pragma unroll
                for (int k = 0; k < 16; k++) {
                    float4 x4 = *(const float4*)&xq[k * SX + d];
                    acc[k] += x4.x * w0 + x4.y * w1 + x4.z * w2 + x4.w * w3;
                }
            }
            #pragma unroll
            for (int j = 0; j < 16; j++) {
                float gv = gZ1[j * SZ + t];
                #pragma unroll
                for (int k = 0; k < 16; k++) acc[k] -= A1[k * 16 + j] * gv;
            }
            #pragma unroll
            for (int k = 0; k < 16; k++) Z1[k * SZ + t] = gelu_f(acc[k]);
        }
        __syncthreads();

        // --- A2 = tril(e*(X2_bar @ X2^T + 1)) ---
        {
            const int ii = t >> 4, jj = t & 15;
            float s = 0.f;
            for (int f = 0; f < 256; f++) s += Z1[ii * SZ + f] * X2[jj * SZ + f];
            A2[ii * 16 + jj] = (jj <= ii) ? tok[ii] * lrs[jj] * (s + 1.0f) : 0.0f;
        }
        __syncthreads();

        // --- Z2_bar = X2_bar @ W2 + b2 - A2 @ gZ2 ---
        {
            const int j = t & 63, rg = t >> 6;
            float acc[4];
            float bv = b2s[j];
            #pragma unroll
            for (int r = 0; r < 4; r++) acc[r] = bv;
            for (int f = 0; f < 256; f++) {
                float w = W2[f * 65 + j];
                #pragma unroll
                for (int r = 0; r < 4; r++) acc[r] += Z1[(rg * 4 + r) * SZ + f] * w;
            }
            #pragma unroll
            for (int jj2 = 0; jj2 < 16; jj2++) {
                float gv = gZ2[jj2 * SX + j];
                #pragma unroll
                for (int r = 0; r < 4; r++) acc[r] -= A2[(rg * 4 + r) * 16 + jj2] * gv;
            }
            #pragma unroll
            for (int r = 0; r < 4; r++) Z2b[(rg * 4 + r) * SX + j] = acc[r];
        }
        __syncthreads();

        // --- state updates ---
        {
            const float lef = tok[15];
            float gcol[16];
            #pragma unroll
            for (int k = 0; k < 16; k++) gcol[k] = lef * lrs[k] * gZ1[k * SZ + t];
            float sb = 0.f;
            #pragma unroll
            for (int k = 0; k < 16; k++) sb += gcol[k];
            b1s[t] -= sb;
            #pragma unroll
            for (int d = 0; d < 64; d += 4) {
                float s0 = 0, s1 = 0, s2 = 0, s3 = 0;
                #pragma unroll
                for (int k = 0; k < 16; k++) {
                    float4 x4 = *(const float4*)&xk[k * SX + d];
                    s0 += gcol[k] * x4.x; s1 += gcol[k] * x4.y;
                    s2 += gcol[k] * x4.z; s3 += gcol[k] * x4.w;
                }
                W1[d * 256 + t]       -= s0;
                W1[(d + 1) * 256 + t] -= s1;
                W1[(d + 2) * 256 + t] -= s2;
                W1[(d + 3) * 256 + t] -= s3;
            }
            const int j = t & 63, fg = t >> 6;
            float hcol[16];
            #pragma unroll
            for (int k = 0; k < 16; k++) hcol[k] = lef * lrs[k] * gZ2[k * SX + j];
            if (fg == 0) {
                float s2b = 0.f;
                #pragma unroll
                for (int k = 0; k < 16; k++) s2b += hcol[k];
                b2s[j] -= s2b;
            }
            for (int f = fg * 64; f < fg * 64 + 64; f++) {
                float s = 0.f;
                #pragma unroll
                for (int k = 0; k < 16; k++) s += hcol[k] * X2[k * SZ + f];
                W2[f * 65 + j] -= s;
            }
        }

        // --- output = xq + ln_fwd(Z2_bar) ---
        #pragma unroll
        for (int rr = 0; rr < 2; rr++) {
            int k = wp * 2 + rr;
            float z0 = Z2b[k * SX + lane], z1 = Z2b[k * SX + lane + 32];
            float mu = wsum(z0 + z1) * (1.0f / 64.0f);
            float d0 = z0 - mu, d1 = z1 - mu;
            float var = wsum(d0 * d0 + d1 * d1) * (1.0f / 64.0f);
            float rstd = rsqrtf(var + 1e-6f);
            g_xqw[cb + k * 64 + lane]      = gam[lane] * d0 * rstd + bet[lane] + xq[k * SX + lane];
            g_xqw[cb + k * 64 + lane + 32] = gam[lane + 32] * d1 * rstd + bet[lane + 32] + xq[k * SX + lane + 32];
        }
        __syncthreads();
    }
}

// ---------------- post layernorm over C ----------------
__global__ __launch_bounds__(256) void postln_kernel(const float* __restrict__ pw,
                                                     const float* __restrict__ pb) {
    const int m = blockIdx.x;
    const int b = m >> 11, l = m & 2047;
    const int n = l >> 4, kk = l & 15;
    __shared__ float row[1024];
    __shared__ float red[18];
    const int t = threadIdx.x;
    for (int i = t; i < 1024; i += 256) {
        int h = i >> 6, d = i & 63;
        row[i] = g_xqw[((((size_t)b * NHc + h) * NCc + n) * Kc + kk) * HDc + d];
    }
    __syncthreads();
    float s = 0.f, ss = 0.f;
    for (int i = t; i < 1024; i += 256) { float v = row[i]; s += v; ss += v * v; }
    s = wsum(s); ss = wsum(ss);
    const int wp = t >> 5, lane = t & 31;
    if (lane == 0) { red[wp] = s; red[8 + wp] = ss; }
    __syncthreads();
    if (t == 0) {
        float S = 0.f, SS = 0.f;
        for (int w = 0; w < 8; w++) { S += red[w]; SS += red[8 + w]; }
        float mu = S * (1.0f / 1024.0f);
        red[16] = mu;
        red[17] = rsqrtf(SS * (1.0f / 1024.0f) - mu * mu + 1e-6f);
    }
    __syncthreads();
    float mu = red[16], rstd = red[17];
    for (int i = t; i < 1024; i += 256)
        g_h2[(size_t)m * 1024 + i] = pw[i] * (row[i] - mu) * rstd + pb[i];
}

// ---------------- launch ----------------
extern "C" void kernel_launch(void* const* d_in, const int* in_sizes, int n_in,
                              void* d_out, int out_size) {
    (void)in_sizes; (void)n_in; (void)out_size;
    const float* hs  = (const float*)d_in[0];
    const float* wq  = (const float*)d_in[1];
    const float* wk  = (const float*)d_in[2];
    const float* wv  = (const float*)d_in[3];
    const float* wo  = (const float*)d_in[4];
    const float* lti = (const float*)d_in[5];
    const float* lrw = (const float*)d_in[6];
    const float* lrb = (const float*)d_in[7];
    const float* nw  = (const float*)d_in[8];
    const float* nb  = (const float*)d_in[9];
    const float* pw  = (const float*)d_in[10];
    const float* pb  = (const float*)d_in[11];
    const float* W1g = (const float*)d_in[12];
    const float* b1g = (const float*)d_in[13];
    const float* W2g = (const float*)d_in[14];
    const float* b2g = (const float*)d_in[15];
    float* out = (float*)d_out;

    cudaFuncSetAttribute(scan_kernel, cudaFuncAttributeMaxDynamicSharedMemorySize,
                         SCAN_SMEM_BYTES);

    gemm_qkv_kernel<<<dim3(16, 128, 3), 256>>>(hs, wq, wk, wv);
    prep_kernel<<<Mtok, 128>>>(hs, lrw, lrb);
    scan_kernel<<<Bc * NHc, 256, SCAN_SMEM_BYTES>>>(lti, W1g, b1g, W2g, b2g, nw, nb);
    postln_kernel<<<Mtok, 256>>>(pw, pb);
    gemm_out_kernel<<<dim3(16, 128, 1), 256>>>(wo, out);
}

// round 3
// speedup vs baseline: 1.2033x; 1.2033x over previous
#include <cuda_runtime.h>
#include <cuda_bf16.h>
#include <math.h>
#include <stdint.h>

// ---------------- problem constants ----------------
constexpr int NHc = 16;
constexpr int HDc = 64;
constexpr int Kc  = 16;
constexpr int Bc  = 4;
constexpr int Lc  = 2048;
constexpr int Cc  = 1024;      // NH*HD
constexpr int NCc = Lc / Kc;   // 128
constexpr int Mtok = Bc * Lc;  // 8192

// ---------------- scratch (device globals; no allocation allowed) ----------
__device__ float g_q [Bc*Lc*Cc];
__device__ float g_k [Bc*Lc*Cc];
__device__ float g_v [Bc*Lc*Cc];
__device__ float g_xq[Bc*Lc*Cc];   // (b,h,n,k,d)
__device__ float g_xk[Bc*Lc*Cc];
__device__ float g_xv[Bc*Lc*Cc];
__device__ float g_xqw[Bc*Lc*Cc];  // scan output (b,h,n,k,d)
__device__ float g_h2[Bc*Lc*Cc];   // post-norm hidden (b,l,c)
__device__ float g_lr[Bc*NHc*NCc*Kc];
// bf16 split operands for tensor-core GEMMs
__device__ __nv_bfloat16 g_ahi[Bc*Lc*Cc];
__device__ __nv_bfloat16 g_alo[Bc*Lc*Cc];
__device__ __nv_bfloat16 g_whi[4*Cc*Cc];
__device__ __nv_bfloat16 g_wlo[4*Cc*Cc];

// ---------------- helpers ----------------
__device__ __forceinline__ float wsum(float v) {
    #pragma unroll
    for (int o = 16; o; o >>= 1) v += __shfl_xor_sync(0xffffffffu, v, o);
    return v;
}
__device__ __forceinline__ float gelu_f(float x) {
    float x2 = x * x;
    float tt = tanhf(0.79788456f * x * (1.0f + 0.044715f * x2));
    return 0.5f * x * (1.0f + tt);
}
__device__ __forceinline__ float gelu_bwd_f(float x) {
    float x2 = x * x;
    float tt = tanhf(0.79788456f * x * (1.0f + 0.044715f * x2));
    return 0.5f * x * ((1.0f - tt * tt) * (0.79788456f + 0.1070322243f * x2))
         + 0.5f * (1.0f + tt);
}
__device__ __forceinline__ uint32_t smem_u32_of(const void* p) {
    uint32_t a;
    asm("{ .reg .u64 t; cvta.to.shared.u64 t, %1; cvt.u32.u64 %0, t; }" : "=r"(a) : "l"(p));
    return a;
}
__device__ __forceinline__ uint32_t lds32(uint32_t a) {
    uint32_t v;
    asm volatile("ld.shared.b32 %0, [%1];" : "=r"(v) : "r"(a));
    return v;
}
__device__ __forceinline__ void cp16(uint32_t dst, const void* src) {
    asm volatile("cp.async.cg.shared.global [%0], [%1], 16;" :: "r"(dst), "l"(src));
}
#define CP_COMMIT() asm volatile("cp.async.commit_group;" ::: "memory")
#define CP_WAIT1()  asm volatile("cp.async.wait_group 1;" ::: "memory")

__device__ __forceinline__ void mma16816(float* c, const uint32_t* a, const uint32_t* b) {
    asm volatile(
        "mma.sync.aligned.m16n8k16.row.col.f32.bf16.bf16.f32 "
        "{%0,%1,%2,%3}, {%4,%5,%6,%7}, {%8,%9}, {%0,%1,%2,%3};"
        : "+f"(c[0]), "+f"(c[1]), "+f"(c[2]), "+f"(c[3])
        : "r"(a[0]), "r"(a[1]), "r"(a[2]), "r"(a[3]), "r"(b[0]), "r"(b[1]));
}

// ---------------- bf16 split kernel: x -> hi + lo ----------------
__global__ __launch_bounds__(256) void split_kernel(const float* __restrict__ src,
                                                    __nv_bfloat16* __restrict__ hi,
                                                    __nv_bfloat16* __restrict__ lo,
                                                    int n4) {
    int i = blockIdx.x * 256 + threadIdx.x;
    if (i >= n4) return;
    float4 v = ((const float4*)src)[i];
    __nv_bfloat16 h0 = __float2bfloat16(v.x), h1 = __float2bfloat16(v.y);
    __nv_bfloat16 h2 = __float2bfloat16(v.z), h3 = __float2bfloat16(v.w);
    __nv_bfloat16 l0 = __float2bfloat16(v.x - __bfloat162float(h0));
    __nv_bfloat16 l1 = __float2bfloat16(v.y - __bfloat162float(h1));
    __nv_bfloat16 l2 = __float2bfloat16(v.z - __bfloat162float(h2));
    __nv_bfloat16 l3 = __float2bfloat16(v.w - __bfloat162float(h3));
    __nv_bfloat162 hA = {h0, h1}, hB = {h2, h3}, lA = {l0, l1}, lB = {l2, l3};
    uint2 hv = {*(uint32_t*)&hA, *(uint32_t*)&hB};
    uint2 lv = {*(uint32_t*)&lA, *(uint32_t*)&lB};
    *(uint2*)(hi + 4 * (size_t)i) = hv;
    *(uint2*)(lo + 4 * (size_t)i) = lv;
}

// ---------------- mma.sync GEMM: C[m][n] = sum_k A[m][k]*W[n][k] ----------------
// 128x128 CTA tile, K-step 32 bf16, 2-stage cp.async pipeline.
// smem rows padded to SB=40 bf16 (80B) -> conflict-free b32 fragment loads.
constexpr int SB = 40;
constexpr int TILE_SM = 128 * SB;                 // bf16 elements per tile
constexpr int GEMM_SMEM = 2 * 4 * TILE_SM * 2;    // 2 stages * 4 tiles * bytes = 81920

__global__ __launch_bounds__(256, 1) void mma_gemm_kernel(
    const __nv_bfloat16* __restrict__ Ahi, const __nv_bfloat16* __restrict__ Alo,
    const __nv_bfloat16* __restrict__ Whi, const __nv_bfloat16* __restrict__ Wlo,
    float* __restrict__ outp, int qkv) {
    extern __shared__ __nv_bfloat16 smem[];
    const uint32_t sm0 = smem_u32_of(smem);

    const int t   = threadIdx.x;
    const int wid = t >> 5, l = t & 31;
    const int m0 = blockIdx.y * 128, n0 = blockIdx.x * 128;
    const int wm = (wid & 1) * 64, wn = (wid >> 1) * 32;

    float* dst = qkv ? ((blockIdx.z == 0) ? g_q : (blockIdx.z == 1) ? g_k : g_v) : outp;
    const __nv_bfloat16* wh = Whi + (size_t)blockIdx.z * (Cc * Cc);
    const __nv_bfloat16* wl = Wlo + (size_t)blockIdx.z * (Cc * Cc);

    const __nv_bfloat16* srcs[4] = {Ahi + (size_t)m0 * 1024, Alo + (size_t)m0 * 1024,
                                    wh + (size_t)n0 * 1024,  wl + (size_t)n0 * 1024};

    float acc[4][4][4];
    #pragma unroll
    for (int i = 0; i < 4; i++)
        #pragma unroll
        for (int j = 0; j < 4; j++)
            #pragma unroll
            for (int r = 0; r < 4; r++) acc[i][j][r] = 0.f;

    // issue loads for k-iteration `it` into stage `s`
    auto issue = [&](int it, int s) {
        const int k0 = it * 32;
        #pragma unroll
        for (int x = 0; x < 8; x++) {
            int ci = x * 256 + t;           // 0..2047
            int tile = ci >> 9, local = ci & 511;
            int row = local >> 2, ch = local & 3;
            const __nv_bfloat16* sp = srcs[tile] + (size_t)row * 1024 + k0 + ch * 8;
            uint32_t dp = sm0 + ((s * 4 + tile) * TILE_SM + row * SB) * 2 + ch * 16;
            cp16(dp, sp);
        }
    };

    issue(0, 0);
    CP_COMMIT();

    for (int it = 0; it < 32; it++) {
        const int s = it & 1;
        if (it + 1 < 32) issue(it + 1, s ^ 1);
        CP_COMMIT();
        CP_WAIT1();
        __syncthreads();

        const uint32_t tAh = sm0 + (s * 4 + 0) * TILE_SM * 2;
        const uint32_t tAl = sm0 + (s * 4 + 1) * TILE_SM * 2;
        const uint32_t tBh = sm0 + (s * 4 + 2) * TILE_SM * 2;
        const uint32_t tBl = sm0 + (s * 4 + 3) * TILE_SM * 2;

        #pragma unroll
        for (int kk = 0; kk < 2; kk++) {
            const uint32_t kel = kk * 16 + (l & 3) * 2;   // element offset in row
            // B fragments (col = n index, k-contiguous rows)
            uint32_t bh[4][2], bl[4][2];
            #pragma unroll
            for (int j = 0; j < 4; j++) {
                uint32_t ro = ((uint32_t)(wn + j * 8 + (l >> 2)) * SB + kel) * 2;
                bh[j][0] = lds32(tBh + ro); bh[j][1] = lds32(tBh + ro + 16);
                bl[j][0] = lds32(tBl + ro); bl[j][1] = lds32(tBl + ro + 16);
            }
            #pragma unroll
            for (int i = 0; i < 4; i++) {
                uint32_t ro = ((uint32_t)(wm + i * 16 + (l >> 2)) * SB + kel) * 2;
                uint32_t ah[4], al[4];
                ah[0] = lds32(tAh + ro);               ah[1] = lds32(tAh + ro + 8 * SB * 2);
                ah[2] = lds32(tAh + ro + 16);          ah[3] = lds32(tAh + ro + 8 * SB * 2 + 16);
                al[0] = lds32(tAl + ro);               al[1] = lds32(tAl + ro + 8 * SB * 2);
                al[2] = lds32(tAl + ro + 16);          al[3] = lds32(tAl + ro + 8 * SB * 2 + 16);
                #pragma unroll
                for (int j = 0; j < 4; j++) {
                    mma16816(acc[i][j], ah, bh[j]);
                    mma16816(acc[i][j], ah, bl[j]);
                    mma16816(acc[i][j], al, bh[j]);
                }
            }
        }
        __syncthreads();
    }

    // epilogue: direct stores
    #pragma unroll
    for (int i = 0; i < 4; i++) {
        const int r0 = m0 + wm + i * 16 + (l >> 2);
        #pragma unroll
        for (int j = 0; j < 4; j++) {
            const int c0 = n0 + wn + j * 8 + (l & 3) * 2;
            float2 v0 = make_float2(acc[i][j][0], acc[i][j][1]);
            float2 v1 = make_float2(acc[i][j][2], acc[i][j][3]);
            *(float2*)(dst + (size_t)r0 * 1024 + c0)       = v0;
            *(float2*)(dst + (size_t)(r0 + 8) * 1024 + c0) = v1;
        }
    }
}

// ---------------- prep: ttt_lr sigmoid + RoPE + relayout --------------------
__global__ __launch_bounds__(128) void prep_kernel(const float* __restrict__ hs,
                                                   const float* __restrict__ lrw,
                                                   const float* __restrict__ lrb) {
    const int m  = blockIdx.x;           // token
    const int b  = m >> 11;
    const int l  = m & 2047;
    const int n  = l >> 4, kk = l & 15;
    __shared__ float xrow[1024];
    const int t = threadIdx.x;
    for (int i = t; i < 1024; i += 128) xrow[i] = hs[(size_t)m * 1024 + i];
    __syncthreads();
    const int wp = t >> 5, lane = t & 31;
    #pragma unroll
    for (int s = 0; s < 4; s++) {
        int h = wp * 4 + s;
        float acc = 0.f;
        for (int c = lane; c < 1024; c += 32) acc += xrow[c] * lrw[h * 1024 + c];
        acc = wsum(acc);
        if (lane == 0) {
            float z = acc + lrb[h];
            g_lr[(((size_t)b * NHc + h) * NCc + n) * Kc + kk] = 1.0f / (1.0f + expf(-z));
        }
    }
    const float pos = (float)kk;
    for (int pr = t; pr < 512; pr += 128) {
        int h = pr >> 5, i = pr & 31;
        float inv = expf(-(float)(2 * i) * (1.0f / 64.0f) * 9.210340371976184f);
        float sn, cs;
        sincosf(pos * inv, &sn, &cs);
        size_t lin = (size_t)m * 1024 + h * 64 + 2 * i;
        size_t so  = ((((size_t)b * NHc + h) * NCc + n) * Kc + kk) * HDc + 2 * i;
        float qe = g_q[lin], qo = g_q[lin + 1];
        g_xq[so]     = qe * cs - qo * sn;
        g_xq[so + 1] = qo * cs + qe * sn;
        float ke = g_k[lin], ko = g_k[lin + 1];
        g_xk[so]     = ke * cs - ko * sn;
        g_xk[so + 1] = ko * cs + ke * sn;
    }
    for (int i = t; i < 1024; i += 128) {
        int h = i >> 6, d = i & 63;
        g_xv[((((size_t)b * NHc + h) * NCc + n) * Kc + kk) * HDc + d] = g_v[(size_t)m * 1024 + i];
    }
}

// ---------------- scan kernel ----------------
constexpr int SX = 68;
constexpr int SZ = 257;
constexpr int SCAN_SMEM_FLOATS =
    64 * 256 + 256 * 65 + 256 + 64 + 64 + 64 + 6 * 16 * SX + 3 * 16 * SZ + 256 + 256 + 16 + 16;
constexpr int SCAN_SMEM_BYTES = SCAN_SMEM_FLOATS * 4;

__global__ __launch_bounds__(256, 1) void scan_kernel(
    const float* __restrict__ lti, const float* __restrict__ W1g,
    const float* __restrict__ b1g, const float* __restrict__ W2g,
    const float* __restrict__ b2g, const float* __restrict__ nw,
    const float* __restrict__ nb) {
    extern __shared__ float sm[];
    float* W1  = sm;                  // [64][256]
    float* W2  = W1 + 64 * 256;       // [256][65]
    float* b1s = W2 + 256 * 65;       // [256]
    float* b2s = b1s + 256;           // [64]
    float* gam = b2s + 64;            // [64]
    float* bet = gam + 64;            // [64]
    float* xq  = bet + 64;            // [16][SX]
    float* xk  = xq + 16 * SX;
    float* xv  = xk + 16 * SX;
    float* Z2  = xv + 16 * SX;
    float* gZ2 = Z2 + 16 * SX;
    float* Z2b = gZ2 + 16 * SX;
    float* Z1  = Z2b + 16 * SX;       // [16][SZ]
    float* X2  = Z1 + 16 * SZ;
    float* gZ1 = X2 + 16 * SZ;
    float* A1  = gZ1 + 16 * SZ;       // [16][16]
    float* A2  = A1 + 256;
    float* lrs = A2 + 256;            // [16]
    float* tok = lrs + 16;            // [16]

    const int t  = threadIdx.x;
    const int bh = blockIdx.x;
    const int hh = bh & 15;
    const int wp = t >> 5, lane = t & 31;

    for (int i = t; i < 64 * 256; i += 256) W1[i] = W1g[hh * 64 * 256 + i];
    for (int i = t; i < 256 * 64; i += 256) W2[(i >> 6) * 65 + (i & 63)] = W2g[hh * 256 * 64 + i];
    b1s[t] = b1g[hh * 256 + t];
    if (t < 64) { b2s[t] = b2g[hh * 64 + t]; gam[t] = nw[hh * 64 + t]; bet[t] = nb[hh * 64 + t]; }
    if (t < 16) tok[t] = fmaxf(1.0f / (float)(t + 1) + lti[t], 0.0f);
    __syncthreads();

    for (int n = 0; n < NCc; n++) {
        const size_t cb = ((size_t)bh * NCc + n) * (Kc * HDc);
        for (int i = t; i < 1024; i += 256) {
            int kk = i >> 6, d = i & 63;
            xq[kk * SX + d] = g_xq[cb + i];
            xk[kk * SX + d] = g_xk[cb + i];
            xv[kk * SX + d] = g_xv[cb + i];
        }
        if (t < 16) lrs[t] = g_lr[((size_t)bh * NCc + n) * Kc + t] * (1.0f / 64.0f);
        __syncthreads();

        // Z1 = xk @ W1 + b1 ; X2 = gelu(Z1)
        {
            float acc[16];
            float bv = b1s[t];
            #pragma unroll
            for (int k = 0; k < 16; k++) acc[k] = bv;
            #pragma unroll
            for (int d = 0; d < 64; d += 4) {
                float w0 = W1[d * 256 + t], w1 = W1[(d + 1) * 256 + t];
                float w2 = W1[(d + 2) * 256 + t], w3 = W1[(d + 3) * 256 + t];
                #pragma unroll
                for (int k = 0; k < 16; k++) {
                    float4 x4 = *(const float4*)&xk[k * SX + d];
                    acc[k] += x4.x * w0 + x4.y * w1 + x4.z * w2 + x4.w * w3;
                }
            }
            #pragma unroll
            for (int k = 0; k < 16; k++) { Z1[k * SZ + t] = acc[k]; X2[k * SZ + t] = gelu_f(acc[k]); }
        }
        __syncthreads();

        // Z2 = X2 @ W2 + b2 ; A1 = tril(e*(xq@xk.T + 1))
        {
            const int j = t & 63, rg = t >> 6;
            float acc[4];
            float bv = b2s[j];
            #pragma unroll
            for (int r = 0; r < 4; r++) acc[r] = bv;
            for (int f = 0; f < 256; f++) {
                float w = W2[f * 65 + j];
                #pragma unroll
                for (int r = 0; r < 4; r++) acc[r] += X2[(rg * 4 + r) * SZ + f] * w;
            }
            #pragma unroll
            for (int r = 0; r < 4; r++) Z2[(rg * 4 + r) * SX + j] = acc[r];

            const int ii = t >> 4, jj = t & 15;
            float s = 0.f;
            #pragma unroll
            for (int d = 0; d < 64; d += 4) {
                float4 a = *(const float4*)&xq[ii * SX + d];
                float4 c = *(const float4*)&xk[jj * SX + d];
                s += a.x * c.x + a.y * c.y + a.z * c.z + a.w * c.w;
            }
            A1[ii * 16 + jj] = (jj <= ii) ? tok[ii] * lrs[jj] * (s + 1.0f) : 0.0f;
        }
        __syncthreads();

        // gZ2 = ln_fused_l2_bwd(Z2, xv-xk)
        #pragma unroll
        for (int rr = 0; rr < 2; rr++) {
            int k = wp * 2 + rr;
            float z0 = Z2[k * SX + lane], z1 = Z2[k * SX + lane + 32];
            float mu = wsum(z0 + z1) * (1.0f / 64.0f);
            float d0 = z0 - mu, d1 = z1 - mu;
            float var = wsum(d0 * d0 + d1 * d1) * (1.0f / 64.0f);
            float rstd = rsqrtf(var + 1e-6f);
            float xh0 = d0 * rstd, xh1 = d1 * rstd;
            float g0 = gam[lane], g1 = gam[lane + 32];
            float be0 = bet[lane], be1 = bet[lane + 32];
            float tg0 = xv[k * SX + lane] - xk[k * SX + lane];
            float tg1 = xv[k * SX + lane + 32] - xk[k * SX + lane + 32];
            float go0 = (g0 * xh0 + be0 - tg0) * g0;
            float go1 = (g1 * xh1 + be1 - tg1) * g1;
            float sgo = wsum(go0 + go1);
            float sgx = wsum(go0 * xh0 + go1 * xh1);
            float cc = rstd * (1.0f / 64.0f);
            gZ2[k * SX + lane]      = (64.0f * go0 - sgo - xh0 * sgx) * cc;
            gZ2[k * SX + lane + 32] = (64.0f * go1 - sgo - xh1 * sgx) * cc;
        }
        __syncthreads();

        // gZ1 = (gZ2 @ W2^T) * gelu_bwd(Z1)
        {
            float acc[16] = {};
            #pragma unroll
            for (int j = 0; j < 64; j += 4) {
                float w0 = W2[t * 65 + j],     w1 = W2[t * 65 + j + 1];
                float w2 = W2[t * 65 + j + 2], w3 = W2[t * 65 + j + 3];
                #pragma unroll
                for (int k = 0; k < 16; k++) {
                    float4 g4 = *(const float4*)&gZ2[k * SX + j];
                    acc[k] += g4.x * w0 + g4.y * w1 + g4.z * w2 + g4.w * w3;
                }
            }
            #pragma unroll
            for (int k = 0; k < 16; k++) gZ1[k * SZ + t] = acc[k] * gelu_bwd_f(Z1[k * SZ + t]);
        }
        __syncthreads();

        // X2_bar = gelu(xq@W1 + b1 - A1@gZ1) -> stored into Z1
        {
            float acc[16];
            float bv = b1s[t];
            #pragma unroll
            for (int k = 0; k < 16; k++) acc[k] = bv;
            #pragma unroll
            for (int d = 0; d < 64; d += 4) {
                float w0 = W1[d * 256 + t], w1 = W1[(d + 1) * 256 + t];
                float w2 = W1[(d + 2) * 256 + t], w3 = W1[(d + 3) * 256 + t];
                #pragma unroll
                for (int k = 0; k < 16; k++) {
                    float4 x4 = *(const float4*)&xq[k * SX + d];
                    acc[k] += x4.x * w0 + x4.y * w1 + x4.z * w2 + x4.w * w3;
                }
            }
            #pragma unroll
            for (int j = 0; j < 16; j++) {
                float gv = gZ1[j * SZ + t];
                #pragma unroll
                for (int k = 0; k < 16; k++) acc[k] -= A1[k * 16 + j] * gv;
            }
            #pragma unroll
            for (int k = 0; k < 16; k++) Z1[k * SZ + t] = gelu_f(acc[k]);
        }
        __syncthreads();

        // A2 = tril(e*(X2_bar @ X2^T + 1))
        {
            const int ii = t >> 4, jj = t & 15;
            float s = 0.f;
            for (int f = 0; f < 256; f++) s += Z1[ii * SZ + f] * X2[jj * SZ + f];
            A2[ii * 16 + jj] = (jj <= ii) ? tok[ii] * lrs[jj] * (s + 1.0f) : 0.0f;
        }
        __syncthreads();

        // Z2_bar = X2_bar @ W2 + b2 - A2 @ gZ2
        {
            const int j = t & 63, rg = t >> 6;
            float acc[4];
            float bv = b2s[j];
            #pragma unroll
            for (int r = 0; r < 4; r++) acc[r] = bv;
            for (int f = 0; f < 256; f++) {
                float w = W2[f * 65 + j];
                #pragma unroll
                for (int r = 0; r < 4; r++) acc[r] += Z1[(rg * 4 + r) * SZ + f] * w;
            }
            #pragma unroll
            for (int jj2 = 0; jj2 < 16; jj2++) {
                float gv = gZ2[jj2 * SX + j];
                #pragma unroll
                for (int r = 0; r < 4; r++) acc[r] -= A2[(rg * 4 + r) * 16 + jj2] * gv;
            }
            #pragma unroll
            for (int r = 0; r < 4; r++) Z2b[(rg * 4 + r) * SX + j] = acc[r];
        }
        __syncthreads();

        // state updates
        {
            const float lef = tok[15];
            float gcol[16];
            #pragma unroll
            for (int k = 0; k < 16; k++) gcol[k] = lef * lrs[k] * gZ1[k * SZ + t];
            float sb = 0.f;
            #pragma unroll
            for (int k = 0; k < 16; k++) sb += gcol[k];
            b1s[t] -= sb;
            #pragma unroll
            for (int d = 0; d < 64; d += 4) {
                float s0 = 0, s1 = 0, s2 = 0, s3 = 0;
                #pragma unroll
                for (int k = 0; k < 16; k++) {
                    float4 x4 = *(const float4*)&xk[k * SX + d];
                    s0 += gcol[k] * x4.x; s1 += gcol[k] * x4.y;
                    s2 += gcol[k] * x4.z; s3 += gcol[k] * x4.w;
                }
                W1[d * 256 + t]       -= s0;
                W1[(d + 1) * 256 + t] -= s1;
                W1[(d + 2) * 256 + t] -= s2;
                W1[(d + 3) * 256 + t] -= s3;
            }
            const int j = t & 63, fg = t >> 6;
            float hcol[16];
            #pragma unroll
            for (int k = 0; k < 16; k++) hcol[k] = lef * lrs[k] * gZ2[k * SX + j];
            if (fg == 0) {
                float s2b = 0.f;
                #pragma unroll
                for (int k = 0; k < 16; k++) s2b += hcol[k];
                b2s[j] -= s2b;
            }
            for (int f = fg * 64; f < fg * 64 + 64; f++) {
                float s = 0.f;
                #pragma unroll
                for (int k = 0; k < 16; k++) s += hcol[k] * X2[k * SZ + f];
                W2[f * 65 + j] -= s;
            }
        }

        // output = xq + ln_fwd(Z2_bar)
        #pragma unroll
        for (int rr = 0; rr < 2; rr++) {
            int k = wp * 2 + rr;
            float z0 = Z2b[k * SX + lane], z1 = Z2b[k * SX + lane + 32];
            float mu = wsum(z0 + z1) * (1.0f / 64.0f);
            float d0 = z0 - mu, d1 = z1 - mu;
            float var = wsum(d0 * d0 + d1 * d1) * (1.0f / 64.0f);
            float rstd = rsqrtf(var + 1e-6f);
            g_xqw[cb + k * 64 + lane]      = gam[lane] * d0 * rstd + bet[lane] + xq[k * SX + lane];
            g_xqw[cb + k * 64 + lane + 32] = gam[lane + 32] * d1 * rstd + bet[lane + 32] + xq[k * SX + lane + 32];
        }
        __syncthreads();
    }
}

// ---------------- post layernorm over C ----------------
__global__ __launch_bounds__(256) void postln_kernel(const float* __restrict__ pw,
                                                     const float* __restrict__ pb) {
    const int m = blockIdx.x;
    const int b = m >> 11, l = m & 2047;
    const int n = l >> 4, kk = l & 15;
    __shared__ float row[1024];
    __shared__ float red[18];
    const int t = threadIdx.x;
    for (int i = t; i < 1024; i += 256) {
        int h = i >> 6, d = i & 63;
        row[i] = g_xqw[((((size_t)b * NHc + h) * NCc + n) * Kc + kk) * HDc + d];
    }
    __syncthreads();
    float s = 0.f, ss = 0.f;
    for (int i = t; i < 1024; i += 256) { float v = row[i]; s += v; ss += v * v; }
    s = wsum(s); ss = wsum(ss);
    const int wp = t >> 5, lane = t & 31;
    if (lane == 0) { red[wp] = s; red[8 + wp] = ss; }
    __syncthreads();
    if (t == 0) {
        float S = 0.f, SS = 0.f;
        for (int w = 0; w < 8; w++) { S += red[w]; SS += red[8 + w]; }
        float mu = S * (1.0f / 1024.0f);
        red[16] = mu;
        red[17] = rsqrtf(SS * (1.0f / 1024.0f) - mu * mu + 1e-6f);
    }
    __syncthreads();
    float mu = red[16], rstd = red[17];
    for (int i = t; i < 1024; i += 256)
        g_h2[(size_t)m * 1024 + i] = pw[i] * (row[i] - mu) * rstd + pb[i];
}

// ---------------- launch ----------------
extern "C" void kernel_launch(void* const* d_in, const int* in_sizes, int n_in,
                              void* d_out, int out_size) {
    (void)in_sizes; (void)n_in; (void)out_size;
    const float* hs  = (const float*)d_in[0];
    const float* wq  = (const float*)d_in[1];
    const float* wk  = (const float*)d_in[2];
    const float* wv  = (const float*)d_in[3];
    const float* wo  = (const float*)d_in[4];
    const float* lti = (const float*)d_in[5];
    const float* lrw = (const float*)d_in[6];
    const float* lrb = (const float*)d_in[7];
    const float* nw  = (const float*)d_in[8];
    const float* nb  = (const float*)d_in[9];
    const float* pw  = (const float*)d_in[10];
    const float* pb  = (const float*)d_in[11];
    const float* W1g = (const float*)d_in[12];
    const float* b1g = (const float*)d_in[13];
    const float* W2g = (const float*)d_in[14];
    const float* b2g = (const float*)d_in[15];
    float* out = (float*)d_out;

    cudaFuncSetAttribute(scan_kernel, cudaFuncAttributeMaxDynamicSharedMemorySize,
                         SCAN_SMEM_BYTES);
    cudaFuncSetAttribute(mma_gemm_kernel, cudaFuncAttributeMaxDynamicSharedMemorySize,
                         GEMM_SMEM);

    void *p_ahi, *p_alo, *p_whi, *p_wlo, *p_h2;
    cudaGetSymbolAddress(&p_ahi, g_ahi);
    cudaGetSymbolAddress(&p_alo, g_alo);
    cudaGetSymbolAddress(&p_whi, g_whi);
    cudaGetSymbolAddress(&p_wlo, g_wlo);
    cudaGetSymbolAddress(&p_h2,  g_h2);
    __nv_bfloat16* ahi = (__nv_bfloat16*)p_ahi;
    __nv_bfloat16* alo = (__nv_bfloat16*)p_alo;
    __nv_bfloat16* whi = (__nv_bfloat16*)p_whi;
    __nv_bfloat16* wlo = (__nv_bfloat16*)p_wlo;

    const int NA4 = (Bc * Lc * Cc) / 4;   // 2,097,152
    const int NW4 = (Cc * Cc) / 4;        // 262,144

    split_kernel<<<(NA4 + 255) / 256, 256>>>(hs, ahi, alo, NA4);
    split_kernel<<<(NW4 + 255) / 256, 256>>>(wq, whi + 0 * Cc * Cc, wlo + 0 * Cc * Cc, NW4);
    split_kernel<<<(NW4 + 255) / 256, 256>>>(wk, whi + 1 * Cc * Cc, wlo + 1 * Cc * Cc, NW4);
    split_kernel<<<(NW4 + 255) / 256, 256>>>(wv, whi + 2 * Cc * Cc, wlo + 2 * Cc * Cc, NW4);
    split_kernel<<<(NW4 + 255) / 256, 256>>>(wo, whi + 3 * Cc * Cc, wlo + 3 * Cc * Cc, NW4);

    mma_gemm_kernel<<<dim3(8, 64, 3), 256, GEMM_SMEM>>>(ahi, alo, whi, wlo, nullptr, 1);
    prep_kernel<<<Mtok, 128>>>(hs, lrw, lrb);
    scan_kernel<<<Bc * NHc, 256, SCAN_SMEM_BYTES>>>(lti, W1g, b1g, W2g, b2g, nw, nb);
    postln_kernel<<<Mtok, 256>>>(pw, pb);

    split_kernel<<<(NA4 + 255) / 256, 256>>>((const float*)p_h2, ahi, alo, NA4);
    // z index 0 must select wo (offset 3): pass shifted weight pointers
    mma_gemm_kernel<<<dim3(8, 64, 1), 256, GEMM_SMEM>>>(ahi, alo,
                                                        whi + 3 * Cc * Cc, wlo + 3 * Cc * Cc,
                                                        out, 0);
}

// round 4
// speedup vs baseline: 1.2100x; 1.0055x over previous
#include <cuda_runtime.h>
#include <cuda_bf16.h>
#include <math.h>
#include <stdint.h>

// ---------------- problem constants ----------------
constexpr int NHc = 16;
constexpr int HDc = 64;
constexpr int Kc  = 16;
constexpr int Bc  = 4;
constexpr int Lc  = 2048;
constexpr int Cc  = 1024;      // NH*HD
constexpr int NCc = Lc / Kc;   // 128
constexpr int Mtok = Bc * Lc;  // 8192

// ---------------- scratch (device globals; no allocation allowed) ----------
__device__ float g_q [Bc*Lc*Cc];
__device__ float g_k [Bc*Lc*Cc];
__device__ float g_v [Bc*Lc*Cc];
__device__ float g_xq[Bc*Lc*Cc];   // (b,h,n,k,d)
__device__ float g_xk[Bc*Lc*Cc];
__device__ float g_xv[Bc*Lc*Cc];
__device__ float g_xqw[Bc*Lc*Cc];  // scan output (b,h,n,k,d)
__device__ float g_h2[Bc*Lc*Cc];   // post-norm hidden (b,l,c)
__device__ float g_lr[Bc*NHc*NCc*Kc];
// bf16 split operands for tensor-core GEMMs
__device__ __nv_bfloat16 g_ahi[Bc*Lc*Cc];
__device__ __nv_bfloat16 g_alo[Bc*Lc*Cc];
__device__ __nv_bfloat16 g_whi[4*Cc*Cc];
__device__ __nv_bfloat16 g_wlo[4*Cc*Cc];

// ---------------- helpers ----------------
__device__ __forceinline__ float wsum(float v) {
    #pragma unroll
    for (int o = 16; o; o >>= 1) v += __shfl_xor_sync(0xffffffffu, v, o);
    return v;
}
__device__ __forceinline__ float gelu_f(float x) {
    float x2 = x * x;
    float tt = tanhf(0.79788456f * x * (1.0f + 0.044715f * x2));
    return 0.5f * x * (1.0f + tt);
}
__device__ __forceinline__ float gelu_bwd_f(float x) {
    float x2 = x * x;
    float tt = tanhf(0.79788456f * x * (1.0f + 0.044715f * x2));
    return 0.5f * x * ((1.0f - tt * tt) * (0.79788456f + 0.1070322243f * x2))
         + 0.5f * (1.0f + tt);
}
__device__ __forceinline__ uint32_t smem_u32_of(const void* p) {
    uint32_t a;
    asm("{ .reg .u64 t; cvta.to.shared.u64 t, %1; cvt.u32.u64 %0, t; }" : "=r"(a) : "l"(p));
    return a;
}
__device__ __forceinline__ uint32_t lds32(uint32_t a) {
    uint32_t v;
    asm volatile("ld.shared.b32 %0, [%1];" : "=r"(v) : "r"(a));
    return v;
}
__device__ __forceinline__ void cp16(uint32_t dst, const void* src) {
    asm volatile("cp.async.cg.shared.global [%0], [%1], 16;" :: "r"(dst), "l"(src));
}
#define CP_COMMIT() asm volatile("cp.async.commit_group;" ::: "memory")
#define CP_WAIT1()  asm volatile("cp.async.wait_group 1;" ::: "memory")

__device__ __forceinline__ void mma16816(float* c, const uint32_t* a, const uint32_t* b) {
    asm volatile(
        "mma.sync.aligned.m16n8k16.row.col.f32.bf16.bf16.f32 "
        "{%0,%1,%2,%3}, {%4,%5,%6,%7}, {%8,%9}, {%0,%1,%2,%3};"
        : "+f"(c[0]), "+f"(c[1]), "+f"(c[2]), "+f"(c[3])
        : "r"(a[0]), "r"(a[1]), "r"(a[2]), "r"(a[3]), "r"(b[0]), "r"(b[1]));
}

// ---------------- bf16 split kernel: x -> hi + lo ----------------
__global__ __launch_bounds__(256) void split_kernel(const float* __restrict__ src,
                                                    __nv_bfloat16* __restrict__ hi,
                                                    __nv_bfloat16* __restrict__ lo,
                                                    int n4) {
    int i = blockIdx.x * 256 + threadIdx.x;
    if (i >= n4) return;
    float4 v = ((const float4*)src)[i];
    __nv_bfloat16 h0 = __float2bfloat16(v.x), h1 = __float2bfloat16(v.y);
    __nv_bfloat16 h2 = __float2bfloat16(v.z), h3 = __float2bfloat16(v.w);
    __nv_bfloat16 l0 = __float2bfloat16(v.x - __bfloat162float(h0));
    __nv_bfloat16 l1 = __float2bfloat16(v.y - __bfloat162float(h1));
    __nv_bfloat16 l2 = __float2bfloat16(v.z - __bfloat162float(h2));
    __nv_bfloat16 l3 = __float2bfloat16(v.w - __bfloat162float(h3));
    __nv_bfloat162 hA = {h0, h1}, hB = {h2, h3}, lA = {l0, l1}, lB = {l2, l3};
    uint2 hv = {*(uint32_t*)&hA, *(uint32_t*)&hB};
    uint2 lv = {*(uint32_t*)&lA, *(uint32_t*)&lB};
    *(uint2*)(hi + 4 * (size_t)i) = hv;
    *(uint2*)(lo + 4 * (size_t)i) = lv;
}

// ---------------- mma.sync GEMM: C[m][n] = sum_k A[m][k]*W[n][k] ----------------
// 128x128 CTA tile, K-step 32 bf16, 2-stage cp.async pipeline.
// smem rows padded to SB=40 bf16 (80B) -> conflict-free b32 fragment loads.
constexpr int SB = 40;
constexpr int TILE_SM = 128 * SB;                 // bf16 elements per tile
constexpr int GEMM_SMEM = 2 * 4 * TILE_SM * 2;    // 2 stages * 4 tiles * bytes = 81920

__global__ __launch_bounds__(256, 1) void mma_gemm_kernel(
    const __nv_bfloat16* __restrict__ Ahi, const __nv_bfloat16* __restrict__ Alo,
    const __nv_bfloat16* __restrict__ Whi, const __nv_bfloat16* __restrict__ Wlo,
    float* __restrict__ outp, int qkv) {
    extern __shared__ __nv_bfloat16 smem[];
    const uint32_t sm0 = smem_u32_of(smem);

    const int t   = threadIdx.x;
    const int wid = t >> 5, l = t & 31;
    const int m0 = blockIdx.y * 128, n0 = blockIdx.x * 128;
    const int wm = (wid & 1) * 64, wn = (wid >> 1) * 32;

    float* dst = qkv ? ((blockIdx.z == 0) ? g_q : (blockIdx.z == 1) ? g_k : g_v) : outp;
    const __nv_bfloat16* wh = Whi + (size_t)blockIdx.z * (Cc * Cc);
    const __nv_bfloat16* wl = Wlo + (size_t)blockIdx.z * (Cc * Cc);

    const __nv_bfloat16* srcs[4] = {Ahi + (size_t)m0 * 1024, Alo + (size_t)m0 * 1024,
                                    wh + (size_t)n0 * 1024,  wl + (size_t)n0 * 1024};

    float acc[4][4][4];
    #pragma unroll
    for (int i = 0; i < 4; i++)
        #pragma unroll
        for (int j = 0; j < 4; j++)
            #pragma unroll
            for (int r = 0; r < 4; r++) acc[i][j][r] = 0.f;

    // issue loads for k-iteration `it` into stage `s`
    auto issue = [&](int it, int s) {
        const int k0 = it * 32;
        #pragma unroll
        for (int x = 0; x < 8; x++) {
            int ci = x * 256 + t;           // 0..2047
            int tile = ci >> 9, local = ci & 511;
            int row = local >> 2, ch = local & 3;
            const __nv_bfloat16* sp = srcs[tile] + (size_t)row * 1024 + k0 + ch * 8;
            uint32_t dp = sm0 + ((s * 4 + tile) * TILE_SM + row * SB) * 2 + ch * 16;
            cp16(dp, sp);
        }
    };

    issue(0, 0);
    CP_COMMIT();

    for (int it = 0; it < 32; it++) {
        const int s = it & 1;
        if (it + 1 < 32) issue(it + 1, s ^ 1);
        CP_COMMIT();
        CP_WAIT1();
        __syncthreads();

        const uint32_t tAh = sm0 + (s * 4 + 0) * TILE_SM * 2;
        const uint32_t tAl = sm0 + (s * 4 + 1) * TILE_SM * 2;
        const uint32_t tBh = sm0 + (s * 4 + 2) * TILE_SM * 2;
        const uint32_t tBl = sm0 + (s * 4 + 3) * TILE_SM * 2;

        #pragma unroll
        for (int kk = 0; kk < 2; kk++) {
            const uint32_t kel = kk * 16 + (l & 3) * 2;   // element offset in row
            // B fragments (col = n index, k-contiguous rows)
            uint32_t bh[4][2], bl[4][2];
            #pragma unroll
            for (int j = 0; j < 4; j++) {
                uint32_t ro = ((uint32_t)(wn + j * 8 + (l >> 2)) * SB + kel) * 2;
                bh[j][0] = lds32(tBh + ro); bh[j][1] = lds32(tBh + ro + 16);
                bl[j][0] = lds32(tBl + ro); bl[j][1] = lds32(tBl + ro + 16);
            }
            #pragma unroll
            for (int i = 0; i < 4; i++) {
                uint32_t ro = ((uint32_t)(wm + i * 16 + (l >> 2)) * SB + kel) * 2;
                uint32_t ah[4], al[4];
                ah[0] = lds32(tAh + ro);               ah[1] = lds32(tAh + ro + 8 * SB * 2);
                ah[2] = lds32(tAh + ro + 16);          ah[3] = lds32(tAh + ro + 8 * SB * 2 + 16);
                al[0] = lds32(tAl + ro);               al[1] = lds32(tAl + ro + 8 * SB * 2);
                al[2] = lds32(tAl + ro + 16);          al[3] = lds32(tAl + ro + 8 * SB * 2 + 16);
                #pragma unroll
                for (int j = 0; j < 4; j++) {
                    mma16816(acc[i][j], ah, bh[j]);
                    mma16816(acc[i][j], ah, bl[j]);
                    mma16816(acc[i][j], al, bh[j]);
                }
            }
        }
        __syncthreads();
    }

    // epilogue: direct stores
    #pragma unroll
    for (int i = 0; i < 4; i++) {
        const int r0 = m0 + wm + i * 16 + (l >> 2);
        #pragma unroll
        for (int j = 0; j < 4; j++) {
            const int c0 = n0 + wn + j * 8 + (l & 3) * 2;
            float2 v0 = make_float2(acc[i][j][0], acc[i][j][1]);
            float2 v1 = make_float2(acc[i][j][2], acc[i][j][3]);
            *(float2*)(dst + (size_t)r0 * 1024 + c0)       = v0;
            *(float2*)(dst + (size_t)(r0 + 8) * 1024 + c0) = v1;
        }
    }
}

// ---------------- prep: ttt_lr sigmoid + RoPE + relayout --------------------
__global__ __launch_bounds__(128) void prep_kernel(const float* __restrict__ hs,
                                                   const float* __restrict__ lrw,
                                                   const float* __restrict__ lrb) {
    const int m  = blockIdx.x;           // token
    const int b  = m >> 11;
    const int l  = m & 2047;
    const int n  = l >> 4, kk = l & 15;
    __shared__ float xrow[1024];
    const int t = threadIdx.x;
    for (int i = t; i < 1024; i += 128) xrow[i] = hs[(size_t)m * 1024 + i];
    __syncthreads();
    const int wp = t >> 5, lane = t & 31;
    #pragma unroll
    for (int s = 0; s < 4; s++) {
        int h = wp * 4 + s;
        float acc = 0.f;
        for (int c = lane; c < 1024; c += 32) acc += xrow[c] * lrw[h * 1024 + c];
        acc = wsum(acc);
        if (lane == 0) {
            float z = acc + lrb[h];
            g_lr[(((size_t)b * NHc + h) * NCc + n) * Kc + kk] = 1.0f / (1.0f + expf(-z));
        }
    }
    const float pos = (float)kk;
    for (int pr = t; pr < 512; pr += 128) {
        int h = pr >> 5, i = pr & 31;
        float inv = expf(-(float)(2 * i) * (1.0f / 64.0f) * 9.210340371976184f);
        float sn, cs;
        sincosf(pos * inv, &sn, &cs);
        size_t lin = (size_t)m * 1024 + h * 64 + 2 * i;
        size_t so  = ((((size_t)b * NHc + h) * NCc + n) * Kc + kk) * HDc + 2 * i;
        float qe = g_q[lin], qo = g_q[lin + 1];
        g_xq[so]     = qe * cs - qo * sn;
        g_xq[so + 1] = qo * cs + qe * sn;
        float ke = g_k[lin], ko = g_k[lin + 1];
        g_xk[so]     = ke * cs - ko * sn;
        g_xk[so + 1] = ko * cs + ke * sn;
    }
    for (int i = t; i < 1024; i += 128) {
        int h = i >> 6, d = i & 63;
        g_xv[((((size_t)b * NHc + h) * NCc + n) * Kc + kk) * HDc + d] = g_v[(size_t)m * 1024 + i];
    }
}

// ---------------- scan kernel ----------------
constexpr int SX = 68;
constexpr int SZ = 257;
constexpr int SCAN_SMEM_FLOATS =
    64 * 256 + 256 * 65 + 256 + 64 + 64 + 64 + 6 * 16 * SX + 3 * 16 * SZ + 256 + 256 + 16 + 16;
constexpr int SCAN_SMEM_BYTES = SCAN_SMEM_FLOATS * 4;

__global__ __launch_bounds__(256, 1) void scan_kernel(
    const float* __restrict__ lti, const float* __restrict__ W1g,
    const float* __restrict__ b1g, const float* __restrict__ W2g,
    const float* __restrict__ b2g, const float* __restrict__ nw,
    const float* __restrict__ nb) {
    extern __shared__ float sm[];
    float* W1  = sm;                  // [64][256]
    float* W2  = W1 + 64 * 256;       // [256][65]
    float* b1s = W2 + 256 * 65;       // [256]
    float* b2s = b1s + 256;           // [64]
    float* gam = b2s + 64;            // [64]
    float* bet = gam + 64;            // [64]
    float* xq  = bet + 64;            // [16][SX]
    float* xk  = xq + 16 * SX;
    float* xv  = xk + 16 * SX;
    float* Z2  = xv + 16 * SX;
    float* gZ2 = Z2 + 16 * SX;
    float* Z2b = gZ2 + 16 * SX;
    float* Z1  = Z2b + 16 * SX;       // [16][SZ]
    float* X2  = Z1 + 16 * SZ;
    float* gZ1 = X2 + 16 * SZ;
    float* A1  = gZ1 + 16 * SZ;       // [16][16]
    float* A2  = A1 + 256;
    float* lrs = A2 + 256;            // [16]
    float* tok = lrs + 16;            // [16]

    const int t  = threadIdx.x;
    const int bh = blockIdx.x;
    const int hh = bh & 15;
    const int wp = t >> 5, lane = t & 31;

    for (int i = t; i < 64 * 256; i += 256) W1[i] = W1g[hh * 64 * 256 + i];
    for (int i = t; i < 256 * 64; i += 256) W2[(i >> 6) * 65 + (i & 63)] = W2g[hh * 256 * 64 + i];
    b1s[t] = b1g[hh * 256 + t];
    if (t < 64) { b2s[t] = b2g[hh * 64 + t]; gam[t] = nw[hh * 64 + t]; bet[t] = nb[hh * 64 + t]; }
    if (t < 16) tok[t] = fmaxf(1.0f / (float)(t + 1) + lti[t], 0.0f);
    __syncthreads();

    for (int n = 0; n < NCc; n++) {
        const size_t cb = ((size_t)bh * NCc + n) * (Kc * HDc);
        for (int i = t; i < 1024; i += 256) {
            int kk = i >> 6, d = i & 63;
            xq[kk * SX + d] = g_xq[cb + i];
            xk[kk * SX + d] = g_xk[cb + i];
            xv[kk * SX + d] = g_xv[cb + i];
        }
        if (t < 16) lrs[t] = g_lr[((size_t)bh * NCc + n) * Kc + t] * (1.0f / 64.0f);
        __syncthreads();

        // Z1 = xk @ W1 + b1 ; X2 = gelu(Z1)
        {
            float acc[16];
            float bv = b1s[t];
            #pragma unroll
            for (int k = 0; k < 16; k++) acc[k] = bv;
            #pragma unroll
            for (int d = 0; d < 64; d += 4) {
                float w0 = W1[d * 256 + t], w1 = W1[(d + 1) * 256 + t];
                float w2 = W1[(d + 2) * 256 + t], w3 = W1[(d + 3) * 256 + t];
                #pragma unroll
                for (int k = 0; k < 16; k++) {
                    float4 x4 = *(const float4*)&xk[k * SX + d];
                    acc[k] += x4.x * w0 + x4.y * w1 + x4.z * w2 + x4.w * w3;
                }
            }
            #pragma unroll
            for (int k = 0; k < 16; k++) { Z1[k * SZ + t] = acc[k]; X2[k * SZ + t] = gelu_f(acc[k]); }
        }
        __syncthreads();

        // Z2 = X2 @ W2 + b2 ; A1 = tril(e*(xq@xk.T + 1))
        {
            const int j = t & 63, rg = t >> 6;
            float acc[4];
            float bv = b2s[j];
            #pragma unroll
            for (int r = 0; r < 4; r++) acc[r] = bv;
            for (int f = 0; f < 256; f++) {
                float w = W2[f * 65 + j];
                #pragma unroll
                for (int r = 0; r < 4; r++) acc[r] += X2[(rg * 4 + r) * SZ + f] * w;
            }
            #pragma unroll
            for (int r = 0; r < 4; r++) Z2[(rg * 4 + r) * SX + j] = acc[r];

            const int ii = t >> 4, jj = t & 15;
            float s = 0.f;
            #pragma unroll
            for (int d = 0; d < 64; d += 4) {
                float4 a = *(const float4*)&xq[ii * SX + d];
                float4 c = *(const float4*)&xk[jj * SX + d];
                s += a.x * c.x + a.y * c.y + a.z * c.z + a.w * c.w;
            }
            A1[ii * 16 + jj] = (jj <= ii) ? tok[ii] * lrs[jj] * (s + 1.0f) : 0.0f;
        }
        __syncthreads();

        // gZ2 = ln_fused_l2_bwd(Z2, xv-xk)
        #pragma unroll
        for (int rr = 0; rr < 2; rr++) {
            int k = wp * 2 + rr;
            float z0 = Z2[k * SX + lane], z1 = Z2[k * SX + lane + 32];
            float mu = wsum(z0 + z1) * (1.0f / 64.0f);
            float d0 = z0 - mu, d1 = z1 - mu;
            float var = wsum(d0 * d0 + d1 * d1) * (1.0f / 64.0f);
            float rstd = rsqrtf(var + 1e-6f);
            float xh0 = d0 * rstd, xh1 = d1 * rstd;
            float g0 = gam[lane], g1 = gam[lane + 32];
            float be0 = bet[lane], be1 = bet[lane + 32];
            float tg0 = xv[k * SX + lane] - xk[k * SX + lane];
            float tg1 = xv[k * SX + lane + 32] - xk[k * SX + lane + 32];
            float go0 = (g0 * xh0 + be0 - tg0) * g0;
            float go1 = (g1 * xh1 + be1 - tg1) * g1;
            float sgo = wsum(go0 + go1);
            float sgx = wsum(go0 * xh0 + go1 * xh1);
            float cc = rstd * (1.0f / 64.0f);
            gZ2[k * SX + lane]      = (64.0f * go0 - sgo - xh0 * sgx) * cc;
            gZ2[k * SX + lane + 32] = (64.0f * go1 - sgo - xh1 * sgx) * cc;
        }
        __syncthreads();

        // gZ1 = (gZ2 @ W2^T) * gelu_bwd(Z1)
        {
            float acc[16] = {};
            #pragma unroll
            for (int j = 0; j < 64; j += 4) {
                float w0 = W2[t * 65 + j],     w1 = W2[t * 65 + j + 1];
                float w2 = W2[t * 65 + j + 2], w3 = W2[t * 65 + j + 3];
                #pragma unroll
                for (int k = 0; k < 16; k++) {
                    float4 g4 = *(const float4*)&gZ2[k * SX + j];
                    acc[k] += g4.x * w0 + g4.y * w1 + g4.z * w2 + g4.w * w3;
                }
            }
            #pragma unroll
            for (int k = 0; k < 16; k++) gZ1[k * SZ + t] = acc[k] * gelu_bwd_f(Z1[k * SZ + t]);
        }
        __syncthreads();

        // X2_bar = gelu(xq@W1 + b1 - A1@gZ1) -> stored into Z1
        {
            float acc[16];
            float bv = b1s[t];
            #pragma unroll
            for (int k = 0; k < 16; k++) acc[k] = bv;
            #pragma unroll
            for (int d = 0; d < 64; d += 4) {
                float w0 = W1[d * 256 + t], w1 = W1[(d + 1) * 256 + t];
                float w2 = W1[(d + 2) * 256 + t], w3 = W1[(d + 3) * 256 + t];
                #pragma unroll
                for (int k = 0; k < 16; k++) {
                    float4 x4 = *(const float4*)&xq[k * SX + d];
                    acc[k] += x4.x * w0 + x4.y * w1 + x4.z * w2 + x4.w * w3;
                }
            }
            #pragma unroll
            for (int j = 0; j < 16; j++) {
                float gv = gZ1[j * SZ + t];
                #pragma unroll
                for (int k = 0; k < 16; k++) acc[k] -= A1[k * 16 + j] * gv;
            }
            #pragma unroll
            for (int k = 0; k < 16; k++) Z1[k * SZ + t] = gelu_f(acc[k]);
        }
        __syncthreads();

        // A2 = tril(e*(X2_bar @ X2^T + 1))
        {
            const int ii = t >> 4, jj = t & 15;
            float s = 0.f;
            for (int f = 0; f < 256; f++) s += Z1[ii * SZ + f] * X2[jj * SZ + f];
            A2[ii * 16 + jj] = (jj <= ii) ? tok[ii] * lrs[jj] * (s + 1.0f) : 0.0f;
        }
        __syncthreads();

        // Z2_bar = X2_bar @ W2 + b2 - A2 @ gZ2
        {
            const int j = t & 63, rg = t >> 6;
            float acc[4];
            float bv = b2s[j];
            #pragma unroll
            for (int r = 0; r < 4; r++) acc[r] = bv;
            for (int f = 0; f < 256; f++) {
                float w = W2[f * 65 + j];
                #pragma unroll
                for (int r = 0; r < 4; r++) acc[r] += Z1[(rg * 4 + r) * SZ + f] * w;
            }
            #pragma unroll
            for (int jj2 = 0; jj2 < 16; jj2++) {
                float gv = gZ2[jj2 * SX + j];
                #pragma unroll
                for (int r = 0; r < 4; r++) acc[r] -= A2[(rg * 4 + r) * 16 + jj2] * gv;
            }
            #pragma unroll
            for (int r = 0; r < 4; r++) Z2b[(rg * 4 + r) * SX + j] = acc[r];
        }
        __syncthreads();

        // state updates
        {
            const float lef = tok[15];
            float gcol[16];
            #pragma unroll
            for (int k = 0; k < 16; k++) gcol[k] = lef * lrs[k] * gZ1[k * SZ + t];
            float sb = 0.f;
            #pragma unroll
            for (int k = 0; k < 16; k++) sb += gcol[k];
            b1s[t] -= sb;
            #pragma unroll
            for (int d = 0; d < 64; d += 4) {
                float s0 = 0, s1 = 0, s2 = 0, s3 = 0;
                #pragma unroll
                for (int k = 0; k < 16; k++) {
                    float4 x4 = *(const float4*)&xk[k * SX + d];
                    s0 += gcol[k] * x4.x; s1 += gcol[k] * x4.y;
                    s2 += gcol[k] * x4.z; s3 += gcol[k] * x4.w;
                }
                W1[d * 256 + t]       -= s0;
                W1[(d + 1) * 256 + t] -= s1;
                W1[(d + 2) * 256 + t] -= s2;
                W1[(d + 3) * 256 + t] -= s3;
            }
            const int j = t & 63, fg = t >> 6;
            float hcol[16];
            #pragma unroll
            for (int k = 0; k < 16; k++) hcol[k] = lef * lrs[k] * gZ2[k * SX + j];
            if (fg == 0) {
                float s2b = 0.f;
                #pragma unroll
                for (int k = 0; k < 16; k++) s2b += hcol[k];
                b2s[j] -= s2b;
            }
            for (int f = fg * 64; f < fg * 64 + 64; f++) {
                float s = 0.f;
                #pragma unroll
                for (int k = 0; k < 16; k++) s += hcol[k] * X2[k * SZ + f];
                W2[f * 65 + j] -= s;
            }
        }

        // output = xq + ln_fwd(Z2_bar)
        #pragma unroll
        for (int rr = 0; rr < 2; rr++) {
            int k = wp * 2 + rr;
            float z0 = Z2b[k * SX + lane], z1 = Z2b[k * SX + lane + 32];
            float mu = wsum(z0 + z1) * (1.0f / 64.0f);
            float d0 = z0 - mu, d1 = z1 - mu;
            float var = wsum(d0 * d0 + d1 * d1) * (1.0f / 64.0f);
            float rstd = rsqrtf(var + 1e-6f);
            g_xqw[cb + k * 64 + lane]      = gam[lane] * d0 * rstd + bet[lane] + xq[k * SX + lane];
            g_xqw[cb + k * 64 + lane + 32] = gam[lane + 32] * d1 * rstd + bet[lane + 32] + xq[k * SX + lane + 32];
        }
        __syncthreads();
    }
}

// ---------------- post layernorm over C ----------------
__global__ __launch_bounds__(256) void postln_kernel(const float* __restrict__ pw,
                                                     const float* __restrict__ pb) {
    const int m = blockIdx.x;
    const int b = m >> 11, l = m & 2047;
    const int n = l >> 4, kk = l & 15;
    __shared__ float row[1024];
    __shared__ float red[18];
    const int t = threadIdx.x;
    for (int i = t; i < 1024; i += 256) {
        int h = i >> 6, d = i & 63;
        row[i] = g_xqw[((((size_t)b * NHc + h) * NCc + n) * Kc + kk) * HDc + d];
    }
    __syncthreads();
    float s = 0.f, ss = 0.f;
    for (int i = t; i < 1024; i += 256) { float v = row[i]; s += v; ss += v * v; }
    s = wsum(s); ss = wsum(ss);
    const int wp = t >> 5, lane = t & 31;
    if (lane == 0) { red[wp] = s; red[8 + wp] = ss; }
    __syncthreads();
    if (t == 0) {
        float S = 0.f, SS = 0.f;
        for (int w = 0; w < 8; w++) { S += red[w]; SS += red[8 + w]; }
        float mu = S * (1.0f / 1024.0f);
        red[16] = mu;
        red[17] = rsqrtf(SS * (1.0f / 1024.0f) - mu * mu + 1e-6f);
    }
    __syncthreads();
    float mu = red[16], rstd = red[17];
    for (int i = t; i < 1024; i += 256)
        g_h2[(size_t)m * 1024 + i] = pw[i] * (row[i] - mu) * rstd + pb[i];
}

// ---------------- launch ----------------
extern "C" void kernel_launch(void* const* d_in, const int* in_sizes, int n_in,
                              void* d_out, int out_size) {
    (void)in_sizes; (void)n_in; (void)out_size;
    const float* hs  = (const float*)d_in[0];
    const float* wq  = (const float*)d_in[1];
    const float* wk  = (const float*)d_in[2];
    const float* wv  = (const float*)d_in[3];
    const float* wo  = (const float*)d_in[4];
    const float* lti = (const float*)d_in[5];
    const float* lrw = (const float*)d_in[6];
    const float* lrb = (const float*)d_in[7];
    const float* nw  = (const float*)d_in[8];
    const float* nb  = (const float*)d_in[9];
    const float* pw  = (const float*)d_in[10];
    const float* pb  = (const float*)d_in[11];
    const float* W1g = (const float*)d_in[12];
    const float* b1g = (const float*)d_in[13];
    const float* W2g = (const float*)d_in[14];
    const float* b2g = (const float*)d_in[15];
    float* out = (float*)d_out;

    cudaFuncSetAttribute(scan_kernel, cudaFuncAttributeMaxDynamicSharedMemorySize,
                         SCAN_SMEM_BYTES);
    cudaFuncSetAttribute(mma_gemm_kernel, cudaFuncAttributeMaxDynamicSharedMemorySize,
                         GEMM_SMEM);

    void *p_ahi, *p_alo, *p_whi, *p_wlo, *p_h2;
    cudaGetSymbolAddress(&p_ahi, g_ahi);
    cudaGetSymbolAddress(&p_alo, g_alo);
    cudaGetSymbolAddress(&p_whi, g_whi);
    cudaGetSymbolAddress(&p_wlo, g_wlo);
    cudaGetSymbolAddress(&p_h2,  g_h2);
    __nv_bfloat16* ahi = (__nv_bfloat16*)p_ahi;
    __nv_bfloat16* alo = (__nv_bfloat16*)p_alo;
    __nv_bfloat16* whi = (__nv_bfloat16*)p_whi;
    __nv_bfloat16* wlo = (__nv_bfloat16*)p_wlo;

    const int NA4 = (Bc * Lc * Cc) / 4;   // 2,097,152
    const int NW4 = (Cc * Cc) / 4;        // 262,144

    split_kernel<<<(NA4 + 255) / 256, 256>>>(hs, ahi, alo, NA4);
    split_kernel<<<(NW4 + 255) / 256, 256>>>(wq, whi + 0 * Cc * Cc, wlo + 0 * Cc * Cc, NW4);
    split_kernel<<<(NW4 + 255) / 256, 256>>>(wk, whi + 1 * Cc * Cc, wlo + 1 * Cc * Cc, NW4);
    split_kernel<<<(NW4 + 255) / 256, 256>>>(wv, whi + 2 * Cc * Cc, wlo + 2 * Cc * Cc, NW4);
    split_kernel<<<(NW4 + 255) / 256, 256>>>(wo, whi + 3 * Cc * Cc, wlo + 3 * Cc * Cc, NW4);

    mma_gemm_kernel<<<dim3(8, 64, 3), 256, GEMM_SMEM>>>(ahi, alo, whi, wlo, nullptr, 1);
    prep_kernel<<<Mtok, 128>>>(hs, lrw, lrb);
    scan_kernel<<<Bc * NHc, 256, SCAN_SMEM_BYTES>>>(lti, W1g, b1g, W2g, b2g, nw, nb);
    postln_kernel<<<Mtok, 256>>>(pw, pb);

    split_kernel<<<(NA4 + 255) / 256, 256>>>((const float*)p_h2, ahi, alo, NA4);
    // z index 0 must select wo (offset 3): pass shifted weight pointers
    mma_gemm_kernel<<<dim3(8, 64, 1), 256, GEMM_SMEM>>>(ahi, alo,
                                                        whi + 3 * Cc * Cc, wlo + 3 * Cc * Cc,
                                                        out, 0);
}

// round 5
// speedup vs baseline: 1.6019x; 1.3239x over previous
#include <cuda_runtime.h>
#include <cuda_bf16.h>
#include <math.h>
#include <stdint.h>

// ---------------- problem constants ----------------
constexpr int NHc = 16;
constexpr int HDc = 64;
constexpr int Kc  = 16;
constexpr int Bc  = 4;
constexpr int Lc  = 2048;
constexpr int Cc  = 1024;      // NH*HD
constexpr int NCc = Lc / Kc;   // 128
constexpr int Mtok = Bc * Lc;  // 8192

// ---------------- scratch (device globals; no allocation allowed) ----------
__device__ float g_q [Bc*Lc*Cc];
__device__ float g_k [Bc*Lc*Cc];
__device__ float g_v [Bc*Lc*Cc];
__device__ float g_xq[Bc*Lc*Cc];   // (b,h,n,k,d)
__device__ float g_xk[Bc*Lc*Cc];
__device__ float g_xv[Bc*Lc*Cc];
__device__ float g_xqw[Bc*Lc*Cc];  // scan output (b,h,n,k,d)
__device__ float g_h2[Bc*Lc*Cc];   // post-norm hidden (b,l,c)
__device__ float g_lr[Bc*NHc*NCc*Kc];
// bf16 split operands for tensor-core GEMMs
__device__ __nv_bfloat16 g_ahi[Bc*Lc*Cc];
__device__ __nv_bfloat16 g_alo[Bc*Lc*Cc];
__device__ __nv_bfloat16 g_whi[4*Cc*Cc];
__device__ __nv_bfloat16 g_wlo[4*Cc*Cc];

// ---------------- helpers ----------------
__device__ __forceinline__ float wsum(float v) {
    #pragma unroll
    for (int o = 16; o; o >>= 1) v += __shfl_xor_sync(0xffffffffu, v, o);
    return v;
}
__device__ __forceinline__ float gelu_f(float x) {
    float x2 = x * x;
    float tt = tanhf(0.79788456f * x * (1.0f + 0.044715f * x2));
    return 0.5f * x * (1.0f + tt);
}
__device__ __forceinline__ float gelu_bwd_f(float x) {
    float x2 = x * x;
    float tt = tanhf(0.79788456f * x * (1.0f + 0.044715f * x2));
    return 0.5f * x * ((1.0f - tt * tt) * (0.79788456f + 0.1070322243f * x2))
         + 0.5f * (1.0f + tt);
}
__device__ __forceinline__ uint32_t smem_u32_of(const void* p) {
    uint32_t a;
    asm("{ .reg .u64 t; cvta.to.shared.u64 t, %1; cvt.u32.u64 %0, t; }" : "=r"(a) : "l"(p));
    return a;
}
__device__ __forceinline__ uint32_t lds32(uint32_t a) {
    uint32_t v;
    asm volatile("ld.shared.b32 %0, [%1];" : "=r"(v) : "r"(a));
    return v;
}
__device__ __forceinline__ void cp16(uint32_t dst, const void* src) {
    asm volatile("cp.async.cg.shared.global [%0], [%1], 16;" :: "r"(dst), "l"(src));
}
#define CP_COMMIT() asm volatile("cp.async.commit_group;" ::: "memory")
#define CP_WAIT1()  asm volatile("cp.async.wait_group 1;" ::: "memory")
#define CP_WAIT0()  asm volatile("cp.async.wait_group 0;" ::: "memory")

// ---- packed f32x2 ops (Blackwell base-family PTX) ----
__device__ __forceinline__ void fma2(unsigned long long& d, unsigned long long a,
                                     unsigned long long b) {
    asm("fma.rn.f32x2 %0, %1, %2, %0;" : "+l"(d) : "l"(a), "l"(b));
}
__device__ __forceinline__ unsigned long long bcast2(float v) {
    unsigned long long r;
    asm("mov.b64 %0, {%1, %1};" : "=l"(r) : "f"(v));
    return r;
}
__device__ __forceinline__ unsigned long long pack2f(float a, float b) {
    unsigned long long r;
    asm("mov.b64 %0, {%1, %2};" : "=l"(r) : "f"(a), "f"(b));
    return r;
}
__device__ __forceinline__ float2 unpack2(unsigned long long v) {
    float2 r;
    asm("mov.b64 {%0, %1}, %2;" : "=f"(r.x), "=f"(r.y) : "l"(v));
    return r;
}
__device__ __forceinline__ float hsum2(unsigned long long v) {
    float2 p = unpack2(v);
    return p.x + p.y;
}

__device__ __forceinline__ void mma16816(float* c, const uint32_t* a, const uint32_t* b) {
    asm volatile(
        "mma.sync.aligned.m16n8k16.row.col.f32.bf16.bf16.f32 "
        "{%0,%1,%2,%3}, {%4,%5,%6,%7}, {%8,%9}, {%0,%1,%2,%3};"
        : "+f"(c[0]), "+f"(c[1]), "+f"(c[2]), "+f"(c[3])
        : "r"(a[0]), "r"(a[1]), "r"(a[2]), "r"(a[3]), "r"(b[0]), "r"(b[1]));
}

// ---------------- bf16 split kernel: x -> hi + lo ----------------
__global__ __launch_bounds__(256) void split_kernel(const float* __restrict__ src,
                                                    __nv_bfloat16* __restrict__ hi,
                                                    __nv_bfloat16* __restrict__ lo,
                                                    int n4) {
    int i = blockIdx.x * 256 + threadIdx.x;
    if (i >= n4) return;
    float4 v = ((const float4*)src)[i];
    __nv_bfloat16 h0 = __float2bfloat16(v.x), h1 = __float2bfloat16(v.y);
    __nv_bfloat16 h2 = __float2bfloat16(v.z), h3 = __float2bfloat16(v.w);
    __nv_bfloat16 l0 = __float2bfloat16(v.x - __bfloat162float(h0));
    __nv_bfloat16 l1 = __float2bfloat16(v.y - __bfloat162float(h1));
    __nv_bfloat16 l2 = __float2bfloat16(v.z - __bfloat162float(h2));
    __nv_bfloat16 l3 = __float2bfloat16(v.w - __bfloat162float(h3));
    __nv_bfloat162 hA = {h0, h1}, hB = {h2, h3}, lA = {l0, l1}, lB = {l2, l3};
    uint2 hv = {*(uint32_t*)&hA, *(uint32_t*)&hB};
    uint2 lv = {*(uint32_t*)&lA, *(uint32_t*)&lB};
    *(uint2*)(hi + 4 * (size_t)i) = hv;
    *(uint2*)(lo + 4 * (size_t)i) = lv;
}

// ---------------- mma.sync GEMM (unchanged from passing R4) ----------------
constexpr int SBg = 40;
constexpr int TILE_SM = 128 * SBg;
constexpr int GEMM_SMEM = 2 * 4 * TILE_SM * 2;

__global__ __launch_bounds__(256, 1) void mma_gemm_kernel(
    const __nv_bfloat16* __restrict__ Ahi, const __nv_bfloat16* __restrict__ Alo,
    const __nv_bfloat16* __restrict__ Whi, const __nv_bfloat16* __restrict__ Wlo,
    float* __restrict__ outp, int qkv) {
    extern __shared__ __nv_bfloat16 smem[];
    const uint32_t sm0 = smem_u32_of(smem);

    const int t   = threadIdx.x;
    const int wid = t >> 5, l = t & 31;
    const int m0 = blockIdx.y * 128, n0 = blockIdx.x * 128;
    const int wm = (wid & 1) * 64, wn = (wid >> 1) * 32;

    float* dst = qkv ? ((blockIdx.z == 0) ? g_q : (blockIdx.z == 1) ? g_k : g_v) : outp;
    const __nv_bfloat16* wh = Whi + (size_t)blockIdx.z * (Cc * Cc);
    const __nv_bfloat16* wl = Wlo + (size_t)blockIdx.z * (Cc * Cc);

    const __nv_bfloat16* srcs[4] = {Ahi + (size_t)m0 * 1024, Alo + (size_t)m0 * 1024,
                                    wh + (size_t)n0 * 1024,  wl + (size_t)n0 * 1024};

    float acc[4][4][4];
    #pragma unroll
    for (int i = 0; i < 4; i++)
        #pragma unroll
        for (int j = 0; j < 4; j++)
            #pragma unroll
            for (int r = 0; r < 4; r++) acc[i][j][r] = 0.f;

    auto issue = [&](int it, int s) {
        const int k0 = it * 32;
        #pragma unroll
        for (int x = 0; x < 8; x++) {
            int ci = x * 256 + t;
            int tile = ci >> 9, local = ci & 511;
            int row = local >> 2, ch = local & 3;
            const __nv_bfloat16* sp = srcs[tile] + (size_t)row * 1024 + k0 + ch * 8;
            uint32_t dp = sm0 + ((s * 4 + tile) * TILE_SM + row * SBg) * 2 + ch * 16;
            cp16(dp, sp);
        }
    };

    issue(0, 0);
    CP_COMMIT();

    for (int it = 0; it < 32; it++) {
        const int s = it & 1;
        if (it + 1 < 32) issue(it + 1, s ^ 1);
        CP_COMMIT();
        CP_WAIT1();
        __syncthreads();

        const uint32_t tAh = sm0 + (s * 4 + 0) * TILE_SM * 2;
        const uint32_t tAl = sm0 + (s * 4 + 1) * TILE_SM * 2;
        const uint32_t tBh = sm0 + (s * 4 + 2) * TILE_SM * 2;
        const uint32_t tBl = sm0 + (s * 4 + 3) * TILE_SM * 2;

        #pragma unroll
        for (int kk = 0; kk < 2; kk++) {
            const uint32_t kel = kk * 16 + (l & 3) * 2;
            uint32_t bh[4][2], bl[4][2];
            #pragma unroll
            for (int j = 0; j < 4; j++) {
                uint32_t ro = ((uint32_t)(wn + j * 8 + (l >> 2)) * SBg + kel) * 2;
                bh[j][0] = lds32(tBh + ro); bh[j][1] = lds32(tBh + ro + 16);
                bl[j][0] = lds32(tBl + ro); bl[j][1] = lds32(tBl + ro + 16);
            }
            #pragma unroll
            for (int i = 0; i < 4; i++) {
                uint32_t ro = ((uint32_t)(wm + i * 16 + (l >> 2)) * SBg + kel) * 2;
                uint32_t ah[4], al[4];
                ah[0] = lds32(tAh + ro);               ah[1] = lds32(tAh + ro + 8 * SBg * 2);
                ah[2] = lds32(tAh + ro + 16);          ah[3] = lds32(tAh + ro + 8 * SBg * 2 + 16);
                al[0] = lds32(tAl + ro);               al[1] = lds32(tAl + ro + 8 * SBg * 2);
                al[2] = lds32(tAl + ro + 16);          al[3] = lds32(tAl + ro + 8 * SBg * 2 + 16);
                #pragma unroll
                for (int j = 0; j < 4; j++) {
                    mma16816(acc[i][j], ah, bh[j]);
                    mma16816(acc[i][j], ah, bl[j]);
                    mma16816(acc[i][j], al, bh[j]);
                }
            }
        }
        __syncthreads();
    }

    #pragma unroll
    for (int i = 0; i < 4; i++) {
        const int r0 = m0 + wm + i * 16 + (l >> 2);
        #pragma unroll
        for (int j = 0; j < 4; j++) {
            const int c0 = n0 + wn + j * 8 + (l & 3) * 2;
            float2 v0 = make_float2(acc[i][j][0], acc[i][j][1]);
            float2 v1 = make_float2(acc[i][j][2], acc[i][j][3]);
            *(float2*)(dst + (size_t)r0 * 1024 + c0)       = v0;
            *(float2*)(dst + (size_t)(r0 + 8) * 1024 + c0) = v1;
        }
    }
}

// ---------------- prep: ttt_lr sigmoid + RoPE + relayout --------------------
__global__ __launch_bounds__(128) void prep_kernel(const float* __restrict__ hs,
                                                   const float* __restrict__ lrw,
                                                   const float* __restrict__ lrb) {
    const int m  = blockIdx.x;
    const int b  = m >> 11;
    const int l  = m & 2047;
    const int n  = l >> 4, kk = l & 15;
    __shared__ float xrow[1024];
    const int t = threadIdx.x;
    for (int i = t; i < 1024; i += 128) xrow[i] = hs[(size_t)m * 1024 + i];
    __syncthreads();
    const int wp = t >> 5, lane = t & 31;
    #pragma unroll
    for (int s = 0; s < 4; s++) {
        int h = wp * 4 + s;
        float acc = 0.f;
        for (int c = lane; c < 1024; c += 32) acc += xrow[c] * lrw[h * 1024 + c];
        acc = wsum(acc);
        if (lane == 0) {
            float z = acc + lrb[h];
            g_lr[(((size_t)b * NHc + h) * NCc + n) * Kc + kk] = 1.0f / (1.0f + expf(-z));
        }
    }
    const float pos = (float)kk;
    for (int pr = t; pr < 512; pr += 128) {
        int h = pr >> 5, i = pr & 31;
        float inv = expf(-(float)(2 * i) * (1.0f / 64.0f) * 9.210340371976184f);
        float sn, cs;
        sincosf(pos * inv, &sn, &cs);
        size_t lin = (size_t)m * 1024 + h * 64 + 2 * i;
        size_t so  = ((((size_t)b * NHc + h) * NCc + n) * Kc + kk) * HDc + 2 * i;
        float qe = g_q[lin], qo = g_q[lin + 1];
        g_xq[so]     = qe * cs - qo * sn;
        g_xq[so + 1] = qo * cs + qe * sn;
        float ke = g_k[lin], ko = g_k[lin + 1];
        g_xk[so]     = ke * cs - ko * sn;
        g_xk[so + 1] = ko * cs + ke * sn;
    }
    for (int i = t; i < 1024; i += 128) {
        int h = i >> 6, d = i & 63;
        g_xv[((((size_t)b * NHc + h) * NCc + n) * Kc + kk) * HDc + d] = g_v[(size_t)m * 1024 + i];
    }
}

// ---------------- scan kernel: 512 threads, f32x2-packed, vector LDS -------
// smem layout (float offsets)
constexpr int O_W1T  = 0;                      // [256][68]  W1T[f][d]
constexpr int O_W2T  = O_W1T + 256 * 68;       // [64][260]  W2T[j][f]
constexpr int O_Z1   = O_W2T + 64 * 260;       // [16][260]  Z1, later X2bar
constexpr int O_X2   = O_Z1 + 16 * 260;        // [16][260]
constexpr int O_GZ1  = O_X2 + 16 * 260;        // [16][260]
constexpr int O_Z2   = O_GZ1 + 16 * 260;       // [16][68]
constexpr int O_Z2B  = O_Z2 + 16 * 68;         // [16][68]
constexpr int O_GZ2T = O_Z2B + 16 * 68;        // [64][20]  gZ2T[j][k]
constexpr int O_A1   = O_GZ2T + 64 * 20;       // [16][20]  (negated)
constexpr int O_A2   = O_A1 + 16 * 20;         // [16][20]  (negated)
constexpr int O_XBUF = O_A2 + 16 * 20;         // 2 stages x {xq,xk,xv} [16][68]
constexpr int XSTAGE = 3 * 16 * 68;            // 3264
constexpr int O_LRS  = O_XBUF + 2 * XSTAGE;    // [2][16]
constexpr int O_TOK  = O_LRS + 32;             // [16]
constexpr int O_B1   = O_TOK + 16;             // [256]
constexpr int O_B2   = O_B1 + 256;             // [64]
constexpr int O_GAM  = O_B2 + 64;              // [64]
constexpr int O_BET  = O_GAM + 64;             // [64]
constexpr int SCAN_SMEM_FLOATS = O_BET + 64;
constexpr int SCAN_SMEM_BYTES  = SCAN_SMEM_FLOATS * 4;   // 230592

__global__ __launch_bounds__(512, 1) void scan_kernel(
    const float* __restrict__ lti, const float* __restrict__ W1g,
    const float* __restrict__ b1g, const float* __restrict__ W2g,
    const float* __restrict__ b2g, const float* __restrict__ nw,
    const float* __restrict__ nb) {
    extern __shared__ float sm[];
    float* W1T  = sm + O_W1T;
    float* W2T  = sm + O_W2T;
    float* Z1   = sm + O_Z1;
    float* X2   = sm + O_X2;
    float* gZ1  = sm + O_GZ1;
    float* Z2   = sm + O_Z2;
    float* Z2b  = sm + O_Z2B;
    float* gZ2T = sm + O_GZ2T;
    float* A1   = sm + O_A1;
    float* A2   = sm + O_A2;
    float* tok64= sm + O_TOK;
    float* b1s  = sm + O_B1;
    float* b2s  = sm + O_B2;
    float* gam  = sm + O_GAM;
    float* bet  = sm + O_BET;

    const uint32_t sm_u = smem_u32_of(sm);
    const int t  = threadIdx.x;
    const int bh = blockIdx.x;
    const int hh = bh & 15;
    const int wp = t >> 5, lane = t & 31;

    // ---- init state (transposed layouts) ----
    for (int i = t; i < 16384; i += 512) {
        int d = i >> 8, f = i & 255;
        W1T[f * 68 + d] = W1g[hh * 16384 + d * 256 + f];
    }
    for (int i = t; i < 16384; i += 512) {
        int f = i >> 6, j = i & 63;
        W2T[j * 260 + f] = W2g[hh * 16384 + f * 64 + j];
    }
    if (t < 256) b1s[t] = b1g[hh * 256 + t];
    if (t < 64) { b2s[t] = b2g[hh * 64 + t]; gam[t] = nw[hh * 64 + t]; bet[t] = nb[hh * 64 + t]; }
    if (t < 16) tok64[t] = fmaxf(1.0f / (float)(t + 1) + lti[t], 0.0f) * (1.0f / 64.0f);

    // ---- stage loader ----
    auto issue_stage = [&](int nn) {
        const int st = nn & 1;
        const size_t cbn = ((size_t)bh * NCc + nn) * (Kc * HDc);
        const uint32_t xbase = sm_u + (O_XBUF + st * XSTAGE) * 4;
        for (int i = t; i < 772; i += 512) {
            if (i < 768) {
                int tile = i >> 8, local = i & 255;
                int row = local >> 4, c4 = local & 15;
                const float* srcb = (tile == 0) ? g_xq : (tile == 1) ? g_xk : g_xv;
                cp16(xbase + (tile * 1088 + row * 68 + c4 * 4) * 4,
                     srcb + cbn + row * 64 + c4 * 4);
            } else {
                int q = i - 768;
                cp16(sm_u + (O_LRS + st * 16 + q * 4) * 4,
                     g_lr + ((size_t)bh * NCc + nn) * Kc + q * 4);
            }
        }
    };

    issue_stage(0);
    CP_COMMIT();
    __syncthreads();

    const int colF = t & 255, halfF = t >> 8;        // 256-col phases
    const int k0F  = halfF * 8;
    const int jj64 = t & 63, rg = t >> 6;            // 64-col phases (rg 0..7)
    const int r0 = rg * 2;

    for (int n = 0; n < NCc; n++) {
        const int st = n & 1;
        float* xq_s = sm + O_XBUF + st * XSTAGE;
        float* xk_s = xq_s + 1088;
        float* xv_s = xk_s + 1088;
        float* lrs  = sm + O_LRS + st * 16;
        const size_t cb = ((size_t)bh * NCc + n) * (Kc * HDc);

        if (n + 1 < NCc) { issue_stage(n + 1); CP_COMMIT(); CP_WAIT1(); }
        else             { CP_WAIT0(); }
        __syncthreads();

        // ---- A: Z1 = xk@W1 + b1 ; X2 = gelu(Z1) ----
        {
            unsigned long long acc[8];
            #pragma unroll
            for (int k = 0; k < 8; k++) acc[k] = 0ull;
            const float* w1r = W1T + colF * 68;
            #pragma unroll 4
            for (int dg = 0; dg < 16; dg++) {
                ulonglong2 wv = *(const ulonglong2*)(w1r + dg * 4);
                #pragma unroll
                for (int k = 0; k < 8; k++) {
                    ulonglong2 xp = *(const ulonglong2*)(xk_s + (k0F + k) * 68 + dg * 4);
                    fma2(acc[k], xp.x, wv.x);
                    fma2(acc[k], xp.y, wv.y);
                }
            }
            float bv = b1s[colF];
            #pragma unroll
            for (int k = 0; k < 8; k++) {
                float s = hsum2(acc[k]) + bv;
                Z1[(k0F + k) * 260 + colF] = s;
                X2[(k0F + k) * 260 + colF] = gelu_f(s);
            }
        }
        __syncthreads();

        // ---- B: Z2 = X2@W2 + b2 ; A1 = -tril(tok*lr*(xq@xk^T + 1)) ----
        {
            unsigned long long a0 = 0ull, a1 = 0ull;
            const float* w2r = W2T + jj64 * 260;
            #pragma unroll 8
            for (int fg = 0; fg < 64; fg++) {
                ulonglong2 wv = *(const ulonglong2*)(w2r + fg * 4);
                ulonglong2 x0 = *(const ulonglong2*)(X2 + r0 * 260 + fg * 4);
                ulonglong2 x1 = *(const ulonglong2*)(X2 + (r0 + 1) * 260 + fg * 4);
                fma2(a0, x0.x, wv.x); fma2(a0, x0.y, wv.y);
                fma2(a1, x1.x, wv.x); fma2(a1, x1.y, wv.y);
            }
            float bv = b2s[jj64];
            Z2[r0 * 68 + jj64]       = hsum2(a0) + bv;
            Z2[(r0 + 1) * 68 + jj64] = hsum2(a1) + bv;

            if (t < 256) {
                const int ii = t >> 4, jj = t & 15;
                unsigned long long ac = 0ull;
                #pragma unroll 4
                for (int dg = 0; dg < 16; dg++) {
                    ulonglong2 qv = *(const ulonglong2*)(xq_s + ii * 68 + dg * 4);
                    ulonglong2 kv = *(const ulonglong2*)(xk_s + jj * 68 + dg * 4);
                    fma2(ac, qv.x, kv.x); fma2(ac, qv.y, kv.y);
                }
                float s = hsum2(ac);
                A1[ii * 20 + jj] = (jj <= ii) ? -(tok64[ii] * lrs[jj] * (s + 1.0f)) : 0.0f;
            }
        }
        __syncthreads();

        // ---- C: gZ2 = ln_fused_l2_bwd(Z2, xv-xk) -> gZ2T[j][k] ----
        {
            int k = wp;
            float z0 = Z2[k * 68 + lane], z1 = Z2[k * 68 + lane + 32];
            float mu = wsum(z0 + z1) * (1.0f / 64.0f);
            float d0 = z0 - mu, d1 = z1 - mu;
            float var = wsum(d0 * d0 + d1 * d1) * (1.0f / 64.0f);
            float rstd = rsqrtf(var + 1e-6f);
            float xh0 = d0 * rstd, xh1 = d1 * rstd;
            float g0 = gam[lane], g1 = gam[lane + 32];
            float be0 = bet[lane], be1 = bet[lane + 32];
            float tg0 = xv_s[k * 68 + lane] - xk_s[k * 68 + lane];
            float tg1 = xv_s[k * 68 + lane + 32] - xk_s[k * 68 + lane + 32];
            float go0 = (g0 * xh0 + be0 - tg0) * g0;
            float go1 = (g1 * xh1 + be1 - tg1) * g1;
            float sgo = wsum(go0 + go1);
            float sgx = wsum(go0 * xh0 + go1 * xh1);
            float cc = rstd * (1.0f / 64.0f);
            gZ2T[lane * 20 + k]        = (64.0f * go0 - sgo - xh0 * sgx) * cc;
            gZ2T[(lane + 32) * 20 + k] = (64.0f * go1 - sgo - xh1 * sgx) * cc;
        }
        __syncthreads();

        // ---- D: gZ1 = (gZ2 @ W2^T) * gelu_bwd(Z1) ----
        {
            unsigned long long acc[4] = {0ull, 0ull, 0ull, 0ull};
            const float* w2c = W2T + colF;
            #pragma unroll 8
            for (int j = 0; j < 64; j++) {
                unsigned long long wpr = bcast2(w2c[j * 260]);
                ulonglong2 ga = *(const ulonglong2*)(gZ2T + j * 20 + k0F);
                ulonglong2 gb = *(const ulonglong2*)(gZ2T + j * 20 + k0F + 4);
                fma2(acc[0], ga.x, wpr); fma2(acc[1], ga.y, wpr);
                fma2(acc[2], gb.x, wpr); fma2(acc[3], gb.y, wpr);
            }
            #pragma unroll
            for (int p = 0; p < 4; p++) {
                float2 g = unpack2(acc[p]);
                int row = k0F + 2 * p;
                gZ1[row * 260 + colF]       = g.x * gelu_bwd_f(Z1[row * 260 + colF]);
                gZ1[(row + 1) * 260 + colF] = g.y * gelu_bwd_f(Z1[(row + 1) * 260 + colF]);
            }
        }
        __syncthreads();

        // ---- E: X2bar = gelu(xq@W1 + b1 + A1neg@gZ1) -> Z1 buffer ----
        {
            unsigned long long acc[8];
            #pragma unroll
            for (int k = 0; k < 8; k++) acc[k] = 0ull;
            const float* w1r = W1T + colF * 68;
            #pragma unroll 4
            for (int dg = 0; dg < 16; dg++) {
                ulonglong2 wv = *(const ulonglong2*)(w1r + dg * 4);
                #pragma unroll
                for (int k = 0; k < 8; k++) {
                    ulonglong2 xp = *(const ulonglong2*)(xq_s + (k0F + k) * 68 + dg * 4);
                    fma2(acc[k], xp.x, wv.x);
                    fma2(acc[k], xp.y, wv.y);
                }
            }
            #pragma unroll
            for (int jp = 0; jp < 8; jp++) {
                unsigned long long gp = pack2f(gZ1[(2 * jp) * 260 + colF],
                                               gZ1[(2 * jp + 1) * 260 + colF]);
                #pragma unroll
                for (int k = 0; k < 8; k++) {
                    unsigned long long ap =
                        *(const unsigned long long*)(A1 + (k0F + k) * 20 + 2 * jp);
                    fma2(acc[k], ap, gp);
                }
            }
            float bv = b1s[colF];
            #pragma unroll
            for (int k = 0; k < 8; k++) {
                float s = hsum2(acc[k]) + bv;
                Z1[(k0F + k) * 260 + colF] = gelu_f(s);   // X2bar
            }
        }
        __syncthreads();

        // ---- F: A2 = -tril(tok*lr*(X2bar@X2^T + 1)) ----
        if (t < 256) {
            const int ii = t >> 4, jj = t & 15;
            unsigned long long ac = 0ull;
            #pragma unroll 8
            for (int fg = 0; fg < 64; fg++) {
                ulonglong2 zb = *(const ulonglong2*)(Z1 + ii * 260 + fg * 4);
                ulonglong2 xo = *(const ulonglong2*)(X2 + jj * 260 + fg * 4);
                fma2(ac, zb.x, xo.x); fma2(ac, zb.y, xo.y);
            }
            float s = hsum2(ac);
            A2[ii * 20 + jj] = (jj <= ii) ? -(tok64[ii] * lrs[jj] * (s + 1.0f)) : 0.0f;
        }
        __syncthreads();

        // ---- G: Z2b = X2bar@W2 + b2 + A2neg@gZ2 ----
        {
            unsigned long long a0 = 0ull, a1 = 0ull;
            const float* w2r = W2T + jj64 * 260;
            #pragma unroll 8
            for (int fg = 0; fg < 64; fg++) {
                ulonglong2 wv = *(const ulonglong2*)(w2r + fg * 4);
                ulonglong2 x0 = *(const ulonglong2*)(Z1 + r0 * 260 + fg * 4);
                ulonglong2 x1 = *(const ulonglong2*)(Z1 + (r0 + 1) * 260 + fg * 4);
                fma2(a0, x0.x, wv.x); fma2(a0, x0.y, wv.y);
                fma2(a1, x1.x, wv.x); fma2(a1, x1.y, wv.y);
            }
            #pragma unroll
            for (int jp = 0; jp < 8; jp++) {
                unsigned long long gp =
                    *(const unsigned long long*)(gZ2T + jj64 * 20 + 2 * jp);
                unsigned long long p0 =
                    *(const unsigned long long*)(A2 + r0 * 20 + 2 * jp);
                unsigned long long p1 =
                    *(const unsigned long long*)(A2 + (r0 + 1) * 20 + 2 * jp);
                fma2(a0, p0, gp);
                fma2(a1, p1, gp);
            }
            float bv = b2s[jj64];
            Z2b[r0 * 68 + jj64]       = hsum2(a0) + bv;
            Z2b[(r0 + 1) * 68 + jj64] = hsum2(a1) + bv;
        }
        __syncthreads();

        // ---- H: state updates ----
        {
            const float lef64 = tok64[15];
            // W1 / b1
            {
                const int d0 = halfF * 32;
                float gc[16]; float sb = 0.f;
                #pragma unroll
                for (int k = 0; k < 16; k++) {
                    gc[k] = lef64 * lrs[k] * gZ1[k * 260 + colF];
                    sb += gc[k];
                }
                if (halfF == 0) b1s[colF] -= sb;
                unsigned long long gneg[16];
                #pragma unroll
                for (int k = 0; k < 16; k++) gneg[k] = bcast2(-gc[k]);
                float* w1r = W1T + colF * 68 + d0;
                #pragma unroll
                for (int dg = 0; dg < 8; dg++) {
                    ulonglong2 acc = *(const ulonglong2*)(w1r + dg * 4);
                    #pragma unroll
                    for (int k = 0; k < 16; k++) {
                        ulonglong2 xp = *(const ulonglong2*)(xk_s + k * 68 + d0 + dg * 4);
                        fma2(acc.x, xp.x, gneg[k]);
                        fma2(acc.y, xp.y, gneg[k]);
                    }
                    *(ulonglong2*)(w1r + dg * 4) = acc;
                }
            }
            // W2 / b2
            {
                const int f0 = rg * 32;
                float hc[16]; float sb2 = 0.f;
                #pragma unroll
                for (int k = 0; k < 16; k++) {
                    hc[k] = lef64 * lrs[k] * gZ2T[jj64 * 20 + k];
                    sb2 += hc[k];
                }
                if (rg == 0) b2s[jj64] -= sb2;
                unsigned long long hneg[16];
                #pragma unroll
                for (int k = 0; k < 16; k++) hneg[k] = bcast2(-hc[k]);
                float* w2r = W2T + jj64 * 260 + f0;
                #pragma unroll
                for (int fg = 0; fg < 8; fg++) {
                    ulonglong2 acc = *(const ulonglong2*)(w2r + fg * 4);
                    #pragma unroll
                    for (int k = 0; k < 16; k++) {
                        ulonglong2 xp = *(const ulonglong2*)(X2 + k * 260 + f0 + fg * 4);
                        fma2(acc.x, xp.x, hneg[k]);
                        fma2(acc.y, xp.y, hneg[k]);
                    }
                    *(ulonglong2*)(w2r + fg * 4) = acc;
                }
            }

            // ---- I: out = xq + ln_fwd(Z2b) ----
            {
                int k = wp;
                float z0 = Z2b[k * 68 + lane], z1 = Z2b[k * 68 + lane + 32];
                float mu = wsum(z0 + z1) * (1.0f / 64.0f);
                float d0 = z0 - mu, d1 = z1 - mu;
                float var = wsum(d0 * d0 + d1 * d1) * (1.0f / 64.0f);
                float rstd = rsqrtf(var + 1e-6f);
                g_xqw[cb + k * 64 + lane] =
                    gam[lane] * d0 * rstd + bet[lane] + xq_s[k * 68 + lane];
                g_xqw[cb + k * 64 + lane + 32] =
                    gam[lane + 32] * d1 * rstd + bet[lane + 32] + xq_s[k * 68 + lane + 32];
            }
        }
        __syncthreads();
    }
}

// ---------------- post layernorm over C ----------------
__global__ __launch_bounds__(256) void postln_kernel(const float* __restrict__ pw,
                                                     const float* __restrict__ pb) {
    const int m = blockIdx.x;
    const int b = m >> 11, l = m & 2047;
    const int n = l >> 4, kk = l & 15;
    __shared__ float row[1024];
    __shared__ float red[18];
    const int t = threadIdx.x;
    for (int i = t; i < 1024; i += 256) {
        int h = i >> 6, d = i & 63;
        row[i] = g_xqw[((((size_t)b * NHc + h) * NCc + n) * Kc + kk) * HDc + d];
    }
    __syncthreads();
    float s = 0.f, ss = 0.f;
    for (int i = t; i < 1024; i += 256) { float v = row[i]; s += v; ss += v * v; }
    s = wsum(s); ss = wsum(ss);
    const int wp = t >> 5, lane = t & 31;
    if (lane == 0) { red[wp] = s; red[8 + wp] = ss; }
    __syncthreads();
    if (t == 0) {
        float S = 0.f, SS = 0.f;
        for (int w = 0; w < 8; w++) { S += red[w]; SS += red[8 + w]; }
        float mu = S * (1.0f / 1024.0f);
        red[16] = mu;
        red[17] = rsqrtf(SS * (1.0f / 1024.0f) - mu * mu + 1e-6f);
    }
    __syncthreads();
    float mu = red[16], rstd = red[17];
    for (int i = t; i < 1024; i += 256)
        g_h2[(size_t)m * 1024 + i] = pw[i] * (row[i] - mu) * rstd + pb[i];
}

// ---------------- launch ----------------
extern "C" void kernel_launch(void* const* d_in, const int* in_sizes, int n_in,
                              void* d_out, int out_size) {
    (void)in_sizes; (void)n_in; (void)out_size;
    const float* hs  = (const float*)d_in[0];
    const float* wq  = (const float*)d_in[1];
    const float* wk  = (const float*)d_in[2];
    const float* wv  = (const float*)d_in[3];
    const float* wo  = (const float*)d_in[4];
    const float* lti = (const float*)d_in[5];
    const float* lrw = (const float*)d_in[6];
    const float* lrb = (const float*)d_in[7];
    const float* nw  = (const float*)d_in[8];
    const float* nb  = (const float*)d_in[9];
    const float* pw  = (const float*)d_in[10];
    const float* pb  = (const float*)d_in[11];
    const float* W1g = (const float*)d_in[12];
    const float* b1g = (const float*)d_in[13];
    const float* W2g = (const float*)d_in[14];
    const float* b2g = (const float*)d_in[15];
    float* out = (float*)d_out;

    cudaFuncSetAttribute(scan_kernel, cudaFuncAttributeMaxDynamicSharedMemorySize,
                         SCAN_SMEM_BYTES);
    cudaFuncSetAttribute(mma_gemm_kernel, cudaFuncAttributeMaxDynamicSharedMemorySize,
                         GEMM_SMEM);

    void *p_ahi, *p_alo, *p_whi, *p_wlo, *p_h2;
    cudaGetSymbolAddress(&p_ahi, g_ahi);
    cudaGetSymbolAddress(&p_alo, g_alo);
    cudaGetSymbolAddress(&p_whi, g_whi);
    cudaGetSymbolAddress(&p_wlo, g_wlo);
    cudaGetSymbolAddress(&p_h2,  g_h2);
    __nv_bfloat16* ahi = (__nv_bfloat16*)p_ahi;
    __nv_bfloat16* alo = (__nv_bfloat16*)p_alo;
    __nv_bfloat16* whi = (__nv_bfloat16*)p_whi;
    __nv_bfloat16* wlo = (__nv_bfloat16*)p_wlo;

    const int NA4 = (Bc * Lc * Cc) / 4;
    const int NW4 = (Cc * Cc) / 4;

    split_kernel<<<(NA4 + 255) / 256, 256>>>(hs, ahi, alo, NA4);
    split_kernel<<<(NW4 + 255) / 256, 256>>>(wq, whi + 0 * Cc * Cc, wlo + 0 * Cc * Cc, NW4);
    split_kernel<<<(NW4 + 255) / 256, 256>>>(wk, whi + 1 * Cc * Cc, wlo + 1 * Cc * Cc, NW4);
    split_kernel<<<(NW4 + 255) / 256, 256>>>(wv, whi + 2 * Cc * Cc, wlo + 2 * Cc * Cc, NW4);
    split_kernel<<<(NW4 + 255) / 256, 256>>>(wo, whi + 3 * Cc * Cc, wlo + 3 * Cc * Cc, NW4);

    mma_gemm_kernel<<<dim3(8, 64, 3), 256, GEMM_SMEM>>>(ahi, alo, whi, wlo, nullptr, 1);
    prep_kernel<<<Mtok, 128>>>(hs, lrw, lrb);
    scan_kernel<<<Bc * NHc, 512, SCAN_SMEM_BYTES>>>(lti, W1g, b1g, W2g, b2g, nw, nb);
    postln_kernel<<<Mtok, 256>>>(pw, pb);

    split_kernel<<<(NA4 + 255) / 256, 256>>>((const float*)p_h2, ahi, alo, NA4);
    mma_gemm_kernel<<<dim3(8, 64, 1), 256, GEMM_SMEM>>>(ahi, alo,
                                                        whi + 3 * Cc * Cc, wlo + 3 * Cc * Cc,
                                                        out, 0);
}